// round 11
// baseline (speedup 1.0000x reference)
#include <cuda_runtime.h>
#include <cuda_bf16.h>
#include <math.h>
#include <stdint.h>

#define B_ 2
#define S_ 2048
#define D_ 1024
#define H_ 16
#define DH_ 64
#define NTOK 4096
#define OUT_ELEMS ((size_t)NTOK * D_)

// ---------------- pre-split bf16 hi/lo scratch -------------------------------
__device__ __nv_bfloat16 g_xs_h[3][(size_t)NTOK * D_];
__device__ __nv_bfloat16 g_xs_l[3][(size_t)NTOK * D_];
__device__ __nv_bfloat16 g_ws_h[4][(size_t)D_ * D_];
__device__ __nv_bfloat16 g_ws_l[4][(size_t)D_ * D_];
__device__ __nv_bfloat16 g_hd_h[3][(size_t)NTOK * D_];   // head-split q/k/v
__device__ __nv_bfloat16 g_hd_l[3][(size_t)NTOK * D_];
__device__ __nv_bfloat16 g_cat_h[(size_t)NTOK * D_];
__device__ __nv_bfloat16 g_cat_l[(size_t)NTOK * D_];

// ---------------- helpers -----------------------------------------------------
__device__ __forceinline__ uint32_t smem_u32(const void* p) {
    uint32_t a;
    asm("{ .reg .u64 t; cvta.to.shared.u64 t, %1; cvt.u32.u64 %0, t; }" : "=r"(a) : "l"(p));
    return a;
}
__device__ __forceinline__ void mma_bf16(float c[4], const uint32_t a[4],
                                         uint32_t b0, uint32_t b1) {
    asm volatile("mma.sync.aligned.m16n8k16.row.col.f32.bf16.bf16.f32 "
        "{%0,%1,%2,%3}, {%4,%5,%6,%7}, {%8,%9}, {%0,%1,%2,%3};"
        : "+f"(c[0]), "+f"(c[1]), "+f"(c[2]), "+f"(c[3])
        : "r"(a[0]), "r"(a[1]), "r"(a[2]), "r"(a[3]), "r"(b0), "r"(b1));
}
__device__ __forceinline__ void ldsm4(uint32_t r[4], uint32_t a) {
    asm volatile("ldmatrix.sync.aligned.m8n8.x4.shared.b16 {%0,%1,%2,%3}, [%4];"
        : "=r"(r[0]), "=r"(r[1]), "=r"(r[2]), "=r"(r[3]) : "r"(a));
}
__device__ __forceinline__ void ldsm4t(uint32_t r[4], uint32_t a) {
    asm volatile("ldmatrix.sync.aligned.m8n8.x4.trans.shared.b16 {%0,%1,%2,%3}, [%4];"
        : "=r"(r[0]), "=r"(r[1]), "=r"(r[2]), "=r"(r[3]) : "r"(a));
}
__device__ __forceinline__ void split2(float x, float y, uint32_t& hi, uint32_t& lo) {
    __nv_bfloat16 hx = __float2bfloat16(x), hy = __float2bfloat16(y);
    __nv_bfloat16 lx = __float2bfloat16(x - __bfloat162float(hx));
    __nv_bfloat16 ly = __float2bfloat16(y - __bfloat162float(hy));
    __nv_bfloat162 h(hx, hy), l(lx, ly);
    hi = *(uint32_t*)&h;
    lo = *(uint32_t*)&l;
}
__device__ __forceinline__ void cp16(uint32_t smem, const void* g) {
    asm volatile("cp.async.cg.shared.global [%0], [%1], 16;" :: "r"(smem), "l"(g));
}
#define CP_COMMIT() asm volatile("cp.async.commit_group;" ::: "memory")
template<int N> __device__ __forceinline__ void cp_wait() {
    asm volatile("cp.async.wait_group %0;" :: "n"(N) : "memory");
}

// ---------------- prep: split inputs + weights --------------------------------
__global__ void __launch_bounds__(256) split_all(
    const float* __restrict__ q, const float* __restrict__ k, const float* __restrict__ v,
    const float* __restrict__ wq, const float* __restrict__ wk,
    const float* __restrict__ wv, const float* __restrict__ wc)
{
    int i = blockIdx.x * 256 + threadIdx.x;          // float4 index
    const float* src;
    __nv_bfloat16 *dh, *dl;
    int off;
    if (i < 3 * 1048576) {
        int ti = i >> 20; off = i & 1048575;
        src = (ti == 0) ? q : (ti == 1) ? k : v;
        dh = g_xs_h[ti]; dl = g_xs_l[ti];
    } else {
        int j = i - 3145728;
        int ti = j >> 18; off = j & 262143;
        src = (ti == 0) ? wq : (ti == 1) ? wk : (ti == 2) ? wv : wc;
        dh = g_ws_h[ti]; dl = g_ws_l[ti];
    }
    float4 x = ((const float4*)src)[off];
    uint32_t h01, l01, h23, l23;
    split2(x.x, x.y, h01, l01);
    split2(x.z, x.w, h23, l23);
    ((uint2*)dh)[off] = make_uint2(h01, h23);
    ((uint2*)dl)[off] = make_uint2(l01, l23);
}

// ---------------- projection GEMM (R5 config: chunk 64, 3-stage, 1 CTA/SM) ----
__global__ void __launch_bounds__(256, 1)
proj_tc(const float* __restrict__ bq, const float* __restrict__ bk,
        const float* __restrict__ bv, const float* __restrict__ bc,
        float* __restrict__ Yout, int mode_base)
{
    extern __shared__ __align__(1024) char smp[];
    uint32_t sb = smem_u32(smp);
    const int t = threadIdx.x, lane = t & 31, wid = t >> 5;
    const int wy = wid >> 2, wx = wid & 3;
    const int mode = mode_base + blockIdx.z;
    const __nv_bfloat16 *Xh, *Xl;
    if (mode < 3) { Xh = g_xs_h[mode]; Xl = g_xs_l[mode]; }
    else          { Xh = g_cat_h;      Xl = g_cat_l; }
    const __nv_bfloat16 *Wh = g_ws_h[mode], *Wl = g_ws_l[mode];
    const float* bias = (mode == 0) ? bq : (mode == 1) ? bk : (mode == 2) ? bv : bc;
    const int bm = blockIdx.y * 128, bn = blockIdx.x * 128;

    float acc[4][4][4];
#pragma unroll
    for (int i = 0; i < 4; i++)
#pragma unroll
        for (int j = 0; j < 4; j++)
#pragma unroll
            for (int k = 0; k < 4; k++) acc[i][j][k] = 0.0f;

#define PJ_PF(c) do { \
    const int kc_ = (c) * 64; \
    uint32_t bo_ = sb + ((c) % 3) * 65536; \
    _Pragma("unroll") \
    for (int i_ = 0; i_ < 4; i_++) { \
        int e_ = i_ * 256 + t, r_ = e_ >> 3, c8_ = e_ & 7; \
        uint32_t so_ = r_ * 128 + ((c8_ ^ (r_ & 7)) << 4); \
        const size_t g_ = (size_t)(bm + r_) * D_ + kc_ + c8_ * 8; \
        cp16(bo_ + so_,         Xh + g_); \
        cp16(bo_ + 16384 + so_, Xl + g_); \
    } \
    _Pragma("unroll") \
    for (int i_ = 0; i_ < 4; i_++) { \
        int e_ = i_ * 256 + t, k_ = e_ >> 4, b_ = e_ & 15; \
        uint32_t so_ = k_ * 256 + ((b_ ^ (k_ & 7)) << 4); \
        const size_t g_ = (size_t)(kc_ + k_) * D_ + bn + b_ * 8; \
        cp16(bo_ + 32768 + so_, Wh + g_); \
        cp16(bo_ + 49152 + so_, Wl + g_); \
    } \
    CP_COMMIT(); \
} while (0)

#define PJ_MMA(base) do { \
    uint32_t aAH = (base), aAL = (base) + 16384, aBH = (base) + 32768, aBL = (base) + 49152; \
    _Pragma("unroll") \
    for (int s = 0; s < 4; s++) { \
        const int rA0 = wy * 64 + ((lane >> 3) & 1) * 8 + (lane & 7); \
        const int cA = 2 * s + (lane >> 4); \
        uint32_t ah[4][4], al[4][4]; \
        _Pragma("unroll") \
        for (int mi = 0; mi < 4; mi++) { \
            int r = rA0 + mi * 16; \
            uint32_t off = r * 128 + ((cA ^ (r & 7)) << 4); \
            ldsm4(ah[mi], aAH + off); \
            ldsm4(al[mi], aAL + off); \
        } \
        const int rB = 16 * s + ((lane >> 3) & 1) * 8 + (lane & 7); \
        uint32_t bh[2][4], bl[2][4]; \
        _Pragma("unroll") \
        for (int nh = 0; nh < 2; nh++) { \
            int cB = ((wx * 32 + nh * 16) >> 3) + ((lane >> 4) & 1); \
            uint32_t off = rB * 256 + ((cB ^ (rB & 7)) << 4); \
            ldsm4t(bh[nh], aBH + off); \
            ldsm4t(bl[nh], aBL + off); \
        } \
        _Pragma("unroll") \
        for (int mi = 0; mi < 4; mi++) \
            _Pragma("unroll") \
            for (int nj = 0; nj < 4; nj++) { \
                uint32_t bh0 = bh[nj >> 1][(nj & 1) * 2], bh1 = bh[nj >> 1][(nj & 1) * 2 + 1]; \
                uint32_t bl0 = bl[nj >> 1][(nj & 1) * 2], bl1 = bl[nj >> 1][(nj & 1) * 2 + 1]; \
                mma_bf16(acc[mi][nj], ah[mi], bh0, bh1); \
                mma_bf16(acc[mi][nj], ah[mi], bl0, bl1); \
                mma_bf16(acc[mi][nj], al[mi], bh0, bh1); \
            } \
    } \
} while (0)

    PJ_PF(0); PJ_PF(1);
#pragma unroll 1
    for (int c = 0; c < 16; c++) {
        if (c + 2 < 16) PJ_PF(c + 2);
        if (c < 14) cp_wait<2>(); else if (c == 14) cp_wait<1>(); else cp_wait<0>();
        __syncthreads();
        PJ_MMA(sb + (c % 3) * 65536);
        __syncthreads();
    }

    const int er = lane >> 2, ec = (lane & 3) * 2;
    if (mode < 3) {
        __nv_bfloat16* dh = g_hd_h[mode];
        __nv_bfloat16* dl = g_hd_l[mode];
#pragma unroll
        for (int mi = 0; mi < 4; mi++)
#pragma unroll
            for (int nj = 0; nj < 4; nj++) {
                const int col = bn + wx * 32 + nj * 8 + ec;
                const float b0 = __ldg(bias + col), b1 = __ldg(bias + col + 1);
                const int row0 = bm + wy * 64 + mi * 16 + er;
#pragma unroll
                for (int h = 0; h < 2; h++) {
                    const int row = row0 + h * 8;
                    uint32_t hv, lv;
                    split2(acc[mi][nj][h * 2] + b0, acc[mi][nj][h * 2 + 1] + b1, hv, lv);
                    int bb = row >> 11, ss = row & (S_ - 1), hh = col >> 6, dd = col & (DH_ - 1);
                    size_t idx = (((size_t)(bb * H_ + hh)) * S_ + ss) * DH_ + dd;
                    *(uint32_t*)(dh + idx) = hv;
                    *(uint32_t*)(dl + idx) = lv;
                }
            }
    } else {
#pragma unroll
        for (int mi = 0; mi < 4; mi++)
#pragma unroll
            for (int nj = 0; nj < 4; nj++) {
                const int col = bn + wx * 32 + nj * 8 + ec;
                const float b0 = __ldg(bias + col), b1 = __ldg(bias + col + 1);
                const int row0 = bm + wy * 64 + mi * 16 + er;
#pragma unroll
                for (int h = 0; h < 2; h++) {
                    float2 v = make_float2(acc[mi][nj][h * 2] + b0, acc[mi][nj][h * 2 + 1] + b1);
                    *(float2*)(Yout + (size_t)(row0 + h * 8) * D_ + col) = v;
                }
            }
    }
}

// ---------------- fused attention (R7 config: 2-pass, merged stats) -----------
// SMEM (96KB):
//  pass1: Q @0 (hi 16K, lo 16K); K buf0 @32K, K buf1 @64K (hi 16K, lo 16K each)
//  pass2: P buf0 @0, P buf1 @32K (hi 16K, lo 16K); V buf0 @64K (hi 8K, lo 8K), buf1 @80K
__global__ void __launch_bounds__(256, 2) fused_attn(float* __restrict__ attn)
{
    extern __shared__ __align__(1024) char smp[];
    __shared__ float2 s_red[128][4];      // (max, sumexp) partials per wx
    __shared__ float sm_m[128], sm_s[128], sm_i[128];
    uint32_t sb = smem_u32(smp);
    const int t = threadIdx.x, lane = t & 31, wid = t >> 5;
    const int bh = blockIdx.y, q0 = blockIdx.x * 128;
    const __nv_bfloat16* Qh = g_hd_h[0] + (size_t)bh * S_ * DH_;
    const __nv_bfloat16* Ql = g_hd_l[0] + (size_t)bh * S_ * DH_;
    const __nv_bfloat16* Kh = g_hd_h[1] + (size_t)bh * S_ * DH_;
    const __nv_bfloat16* Kl = g_hd_l[1] + (size_t)bh * S_ * DH_;
    const __nv_bfloat16* Vh = g_hd_h[2] + (size_t)bh * S_ * DH_;
    const __nv_bfloat16* Vl = g_hd_l[2] + (size_t)bh * S_ * DH_;
    float* A = attn + (size_t)bh * S_ * S_;

    if (t < 128) { sm_m[t] = -1e30f; sm_s[t] = 0.0f; }

    // ---- load Q (group with K0) ----
#pragma unroll
    for (int i = 0; i < 4; i++) {
        int e = i * 256 + t, r = e >> 3, c8 = e & 7;
        uint32_t so = r * 128 + ((c8 ^ (r & 7)) << 4);
        cp16(sb + so,         Qh + (size_t)(q0 + r) * DH_ + c8 * 8);
        cp16(sb + 16384 + so, Ql + (size_t)(q0 + r) * DH_ + c8 * 8);
    }
#define FA_KPF(kt) do { \
    uint32_t kb_ = sb + 32768 + ((kt) & 1) * 32768; \
    _Pragma("unroll") \
    for (int i_ = 0; i_ < 4; i_++) { \
        int e_ = i_ * 256 + t, r_ = e_ >> 3, c8_ = e_ & 7; \
        uint32_t so_ = r_ * 128 + ((c8_ ^ (r_ & 7)) << 4); \
        cp16(kb_ + so_,         Kh + (size_t)((kt) * 128 + r_) * DH_ + c8_ * 8); \
        cp16(kb_ + 16384 + so_, Kl + (size_t)((kt) * 128 + r_) * DH_ + c8_ * 8); \
    } \
    CP_COMMIT(); \
} while (0)

    FA_KPF(0);          // group0 = Q + K0
    FA_KPF(1);          // group1 = K1

    // ================= PASS 1: S = 0.125 * Q K^T, online stats =================
    {
        const int wy = wid >> 2, wx = wid & 3;       // 2 x 4 warps, warp 64q x 32k
        const int er = lane >> 2, ec = (lane & 3) * 2;
#pragma unroll 1
        for (int kt = 0; kt < 16; kt++) {
            if (kt == 15) cp_wait<0>(); else cp_wait<1>();
            __syncthreads();                          // also protects s_red reuse

            float acc[4][4][4];
#pragma unroll
            for (int i = 0; i < 4; i++)
#pragma unroll
                for (int j = 0; j < 4; j++)
#pragma unroll
                    for (int k = 0; k < 4; k++) acc[i][j][k] = 0.0f;

            const uint32_t aQH = sb, aQL = sb + 16384;
            const uint32_t aKH = sb + 32768 + (kt & 1) * 32768, aKL = aKH + 16384;
#pragma unroll
            for (int s = 0; s < 4; s++) {
                const int rA0 = wy * 64 + ((lane >> 3) & 1) * 8 + (lane & 7);
                const int cA = 2 * s + (lane >> 4);
                uint32_t ah[4][4], al[4][4];
#pragma unroll
                for (int mi = 0; mi < 4; mi++) {
                    int r = rA0 + mi * 16;
                    uint32_t off = r * 128 + ((cA ^ (r & 7)) << 4);
                    ldsm4(ah[mi], aQH + off);
                    ldsm4(al[mi], aQL + off);
                }
                uint32_t bhf[2][4], blf[2][4];
                const int cB = 2 * s + ((lane >> 3) & 1);
#pragma unroll
                for (int nh = 0; nh < 2; nh++) {
                    int r = wx * 32 + nh * 16 + ((lane >> 4) & 1) * 8 + (lane & 7);
                    uint32_t off = r * 128 + ((cB ^ (r & 7)) << 4);
                    ldsm4(bhf[nh], aKH + off);
                    ldsm4(blf[nh], aKL + off);
                }
#pragma unroll
                for (int mi = 0; mi < 4; mi++)
#pragma unroll
                    for (int nj = 0; nj < 4; nj++) {
                        uint32_t b0 = bhf[nj >> 1][(nj & 1) * 2], b1 = bhf[nj >> 1][(nj & 1) * 2 + 1];
                        uint32_t c0 = blf[nj >> 1][(nj & 1) * 2], c1 = blf[nj >> 1][(nj & 1) * 2 + 1];
                        mma_bf16(acc[mi][nj], ah[mi], b0, b1);
                        mma_bf16(acc[mi][nj], ah[mi], c0, c1);
                        mma_bf16(acc[mi][nj], al[mi], b0, b1);
                    }
            }
#pragma unroll
            for (int i = 0; i < 4; i++)
#pragma unroll
                for (int j = 0; j < 4; j++)
#pragma unroll
                    for (int k = 0; k < 4; k++) acc[i][j][k] *= 0.125f;

            // warp-local (max, sumexp) partials — one pass, one sync
#pragma unroll
            for (int mi = 0; mi < 4; mi++)
#pragma unroll
                for (int h = 0; h < 2; h++) {
                    float m = -1e30f;
#pragma unroll
                    for (int nj = 0; nj < 4; nj++)
                        m = fmaxf(m, fmaxf(acc[mi][nj][h * 2], acc[mi][nj][h * 2 + 1]));
                    m = fmaxf(m, __shfl_xor_sync(0xffffffffu, m, 1));
                    m = fmaxf(m, __shfl_xor_sync(0xffffffffu, m, 2));
                    float s = 0.0f;
#pragma unroll
                    for (int nj = 0; nj < 4; nj++)
                        s += __expf(acc[mi][nj][h * 2] - m) + __expf(acc[mi][nj][h * 2 + 1] - m);
                    s += __shfl_xor_sync(0xffffffffu, s, 1);
                    s += __shfl_xor_sync(0xffffffffu, s, 2);
                    if ((lane & 3) == 0)
                        s_red[wy * 64 + mi * 16 + h * 8 + er][wx] = make_float2(m, s);
                }
            __syncthreads();
            if (t < 128) {
                float2 p0 = s_red[t][0], p1 = s_red[t][1], p2 = s_red[t][2], p3 = s_red[t][3];
                float mt = fmaxf(fmaxf(p0.x, p1.x), fmaxf(p2.x, p3.x));
                float st = p0.y * __expf(p0.x - mt) + p1.y * __expf(p1.x - mt)
                         + p2.y * __expf(p2.x - mt) + p3.y * __expf(p3.x - mt);
                float mo = sm_m[t];
                float mn = fmaxf(mo, mt);
                sm_s[t] = sm_s[t] * __expf(mo - mn) + st * __expf(mt - mn);
                sm_m[t] = mn;
            }
            // write raw S tile
            const int k0 = kt * 128;
#pragma unroll
            for (int mi = 0; mi < 4; mi++)
#pragma unroll
                for (int nj = 0; nj < 4; nj++) {
                    const int col = k0 + wx * 32 + nj * 8 + ec;
                    const int row0 = q0 + wy * 64 + mi * 16 + er;
#pragma unroll
                    for (int h = 0; h < 2; h++) {
                        float2 v = make_float2(acc[mi][nj][h * 2], acc[mi][nj][h * 2 + 1]);
                        *(float2*)(A + (size_t)(row0 + h * 8) * S_ + col) = v;
                    }
                }
            if (kt + 2 < 16) FA_KPF(kt + 2);
        }
    }
    __syncthreads();
    if (t < 128) sm_i[t] = 1.0f / sm_s[t];
    __syncthreads();

    // ================= PASS 2: p = exp(S-m)*inv ; O = p @ V ====================
    {
        const int wy = wid >> 1, wx = wid & 1;       // 4 x 2 warps, warp 32q x 32d
        float acc[2][4][4];
#pragma unroll
        for (int i = 0; i < 2; i++)
#pragma unroll
            for (int j = 0; j < 4; j++)
#pragma unroll
                for (int k = 0; k < 4; k++) acc[i][j][k] = 0.0f;

        float4 ra[8];
        const int arow = t >> 4, ac4 = t & 15;

#define FA_VPF(c) do { \
    const int kc_ = (c) * 64; \
    uint32_t vb_ = sb + 65536 + ((c) & 1) * 16384; \
    _Pragma("unroll") \
    for (int i_ = 0; i_ < 2; i_++) { \
        int e_ = i_ * 256 + t, r_ = e_ >> 3, c8_ = e_ & 7; \
        uint32_t so_ = r_ * 128 + ((c8_ ^ (r_ & 7)) << 4); \
        cp16(vb_ + so_,        Vh + (size_t)(kc_ + r_) * DH_ + c8_ * 8); \
        cp16(vb_ + 8192 + so_, Vl + (size_t)(kc_ + r_) * DH_ + c8_ * 8); \
    } \
    CP_COMMIT(); \
} while (0)

#define FA_LDA(c) do { \
    const int kc_ = (c) * 64; \
    _Pragma("unroll") \
    for (int i_ = 0; i_ < 8; i_++) \
        ra[i_] = *(const float4*)(A + (size_t)(q0 + i_ * 16 + arow) * S_ + kc_ + ac4 * 4); \
} while (0)

#define FA_STA(c) do { \
    const int kc_ = (c) * 64; \
    char* ab_ = smp + ((c) & 1) * 32768; \
    _Pragma("unroll") \
    for (int i_ = 0; i_ < 8; i_++) { \
        int r_ = i_ * 16 + arow; \
        const float m_ = sm_m[r_], in_ = sm_i[r_]; \
        float4 p_; \
        p_.x = __expf(ra[i_].x - m_) * in_; \
        p_.y = __expf(ra[i_].y - m_) * in_; \
        p_.z = __expf(ra[i_].z - m_) * in_; \
        p_.w = __expf(ra[i_].w - m_) * in_; \
        *(float4*)(A + (size_t)(q0 + r_) * S_ + kc_ + ac4 * 4) = p_; \
        uint32_t h01, l01, h23, l23; \
        split2(p_.x, p_.y, h01, l01); \
        split2(p_.z, p_.w, h23, l23); \
        uint32_t so_ = r_ * 128 + ((((ac4 >> 1) ^ (r_ & 7)) << 4)) + (ac4 & 1) * 8; \
        *(uint2*)(ab_ + so_)         = make_uint2(h01, h23); \
        *(uint2*)(ab_ + 16384 + so_) = make_uint2(l01, l23); \
    } \
} while (0)

#define FA_MMA(c) do { \
    uint32_t aAH = sb + ((c) & 1) * 32768, aAL = aAH + 16384; \
    uint32_t aBH = sb + 65536 + ((c) & 1) * 16384, aBL = aBH + 8192; \
    _Pragma("unroll") \
    for (int s = 0; s < 4; s++) { \
        const int rA0 = wy * 32 + ((lane >> 3) & 1) * 8 + (lane & 7); \
        const int cA = 2 * s + (lane >> 4); \
        uint32_t ah[2][4], al[2][4]; \
        _Pragma("unroll") \
        for (int mi = 0; mi < 2; mi++) { \
            int r = rA0 + mi * 16; \
            uint32_t off = r * 128 + ((cA ^ (r & 7)) << 4); \
            ldsm4(ah[mi], aAH + off); \
            ldsm4(al[mi], aAL + off); \
        } \
        const int rB = 16 * s + ((lane >> 3) & 1) * 8 + (lane & 7); \
        uint32_t bh2[2][4], bl2[2][4]; \
        _Pragma("unroll") \
        for (int nh = 0; nh < 2; nh++) { \
            int cB = ((wx * 32 + nh * 16) >> 3) + ((lane >> 4) & 1); \
            uint32_t off = rB * 128 + ((cB ^ (rB & 7)) << 4); \
            ldsm4t(bh2[nh], aBH + off); \
            ldsm4t(bl2[nh], aBL + off); \
        } \
        _Pragma("unroll") \
        for (int mi = 0; mi < 2; mi++) \
            _Pragma("unroll") \
            for (int nj = 0; nj < 4; nj++) { \
                uint32_t b0 = bh2[nj >> 1][(nj & 1) * 2], b1 = bh2[nj >> 1][(nj & 1) * 2 + 1]; \
                uint32_t c0 = bl2[nj >> 1][(nj & 1) * 2], c1 = bl2[nj >> 1][(nj & 1) * 2 + 1]; \
                mma_bf16(acc[mi][nj], ah[mi], b0, b1); \
                mma_bf16(acc[mi][nj], ah[mi], c0, c1); \
                mma_bf16(acc[mi][nj], al[mi], b0, b1); \
            } \
    } \
} while (0)

        // reverse order: most recently written S tiles are read first (L2 warm)
        FA_VPF(31);
        FA_LDA(31);
        FA_STA(31);
#pragma unroll 1
        for (int c = 31; c >= 0; c--) {
            if (c > 0) { FA_VPF(c - 1); FA_LDA(c - 1); }
            if (c > 0) cp_wait<1>(); else cp_wait<0>();
            __syncthreads();
            FA_MMA(c);
            if (c > 0) FA_STA(c - 1);
            __syncthreads();
        }

        const int bb = bh >> 4, hh = bh & (H_ - 1);
        const int er = lane >> 2, ec = (lane & 3) * 2;
#pragma unroll
        for (int mi = 0; mi < 2; mi++)
#pragma unroll
            for (int nj = 0; nj < 4; nj++) {
                const int dd = wx * 32 + nj * 8 + ec;
                const int row0 = q0 + wy * 32 + mi * 16 + er;
#pragma unroll
                for (int h = 0; h < 2; h++) {
                    const int ss = row0 + h * 8;
                    uint32_t hv, lv;
                    split2(acc[mi][nj][h * 2], acc[mi][nj][h * 2 + 1], hv, lv);
                    size_t idx = ((size_t)(bb * S_ + ss)) * D_ + hh * DH_ + dd;
                    *(uint32_t*)(g_cat_h + idx) = hv;
                    *(uint32_t*)(g_cat_l + idx) = lv;
                }
            }
    }
}

// ---------------- launch ------------------------------------------------------
extern "C" void kernel_launch(void* const* d_in, const int* in_sizes, int n_in,
                              void* d_out, int out_size)
{
    const float* q  = (const float*)d_in[0];
    const float* k  = (const float*)d_in[1];
    const float* v  = (const float*)d_in[2];
    const float* Wq = (const float*)d_in[3];
    const float* bq = (const float*)d_in[4];
    const float* Wk = (const float*)d_in[5];
    const float* bk = (const float*)d_in[6];
    const float* Wv = (const float*)d_in[7];
    const float* bv = (const float*)d_in[8];
    const float* Wc = (const float*)d_in[9];
    const float* bc = (const float*)d_in[10];

    float* out  = (float*)d_out;
    float* attn = out + OUT_ELEMS;

    const int SM_PROJ = 196608;
    const int SM_FA   = 98304;
    cudaFuncSetAttribute(proj_tc,    cudaFuncAttributeMaxDynamicSharedMemorySize, SM_PROJ);
    cudaFuncSetAttribute(fused_attn, cudaFuncAttributeMaxDynamicSharedMemorySize, SM_FA);

    split_all<<<16384, 256>>>(q, k, v, Wq, Wk, Wv, Wc);

    proj_tc<<<dim3(8, 32, 3), 256, SM_PROJ>>>(bq, bk, bv, bc, nullptr, 0);

    fused_attn<<<dim3(16, 32), 256, SM_FA>>>(attn);

    proj_tc<<<dim3(8, 32, 1), 256, SM_PROJ>>>(bq, bk, bv, bc, out, 3);
}

// round 12
// speedup vs baseline: 1.5060x; 1.5060x over previous
#include <cuda_runtime.h>
#include <cuda_bf16.h>
#include <math.h>
#include <stdint.h>

#define B_ 2
#define S_ 2048
#define D_ 1024
#define H_ 16
#define DH_ 64
#define NTOK 4096
#define OUT_ELEMS ((size_t)NTOK * D_)

// ---------------- pre-split bf16 hi/lo scratch -------------------------------
__device__ __nv_bfloat16 g_xs_h[3][(size_t)NTOK * D_];
__device__ __nv_bfloat16 g_xs_l[3][(size_t)NTOK * D_];
__device__ __nv_bfloat16 g_ws_h[4][(size_t)D_ * D_];
__device__ __nv_bfloat16 g_ws_l[4][(size_t)D_ * D_];
__device__ __nv_bfloat16 g_hd_h[3][(size_t)NTOK * D_];   // head-split q/k/v (q pre-scaled 0.125)
__device__ __nv_bfloat16 g_hd_l[3][(size_t)NTOK * D_];
__device__ __nv_bfloat16 g_cat_h[(size_t)NTOK * D_];
__device__ __nv_bfloat16 g_cat_l[(size_t)NTOK * D_];

// ---------------- helpers -----------------------------------------------------
__device__ __forceinline__ uint32_t smem_u32(const void* p) {
    uint32_t a;
    asm("{ .reg .u64 t; cvta.to.shared.u64 t, %1; cvt.u32.u64 %0, t; }" : "=r"(a) : "l"(p));
    return a;
}
__device__ __forceinline__ void mma_bf16(float c[4], const uint32_t a[4],
                                         uint32_t b0, uint32_t b1) {
    asm volatile("mma.sync.aligned.m16n8k16.row.col.f32.bf16.bf16.f32 "
        "{%0,%1,%2,%3}, {%4,%5,%6,%7}, {%8,%9}, {%0,%1,%2,%3};"
        : "+f"(c[0]), "+f"(c[1]), "+f"(c[2]), "+f"(c[3])
        : "r"(a[0]), "r"(a[1]), "r"(a[2]), "r"(a[3]), "r"(b0), "r"(b1));
}
__device__ __forceinline__ void ldsm4(uint32_t r[4], uint32_t a) {
    asm volatile("ldmatrix.sync.aligned.m8n8.x4.shared.b16 {%0,%1,%2,%3}, [%4];"
        : "=r"(r[0]), "=r"(r[1]), "=r"(r[2]), "=r"(r[3]) : "r"(a));
}
__device__ __forceinline__ void ldsm4t(uint32_t r[4], uint32_t a) {
    asm volatile("ldmatrix.sync.aligned.m8n8.x4.trans.shared.b16 {%0,%1,%2,%3}, [%4];"
        : "=r"(r[0]), "=r"(r[1]), "=r"(r[2]), "=r"(r[3]) : "r"(a));
}
__device__ __forceinline__ void split2(float x, float y, uint32_t& hi, uint32_t& lo) {
    __nv_bfloat16 hx = __float2bfloat16(x), hy = __float2bfloat16(y);
    __nv_bfloat16 lx = __float2bfloat16(x - __bfloat162float(hx));
    __nv_bfloat16 ly = __float2bfloat16(y - __bfloat162float(hy));
    __nv_bfloat162 h(hx, hy), l(lx, ly);
    hi = *(uint32_t*)&h;
    lo = *(uint32_t*)&l;
}
__device__ __forceinline__ void cp16(uint32_t smem, const void* g) {
    asm volatile("cp.async.cg.shared.global [%0], [%1], 16;" :: "r"(smem), "l"(g));
}
#define CP_COMMIT() asm volatile("cp.async.commit_group;" ::: "memory")
template<int N> __device__ __forceinline__ void cp_wait() {
    asm volatile("cp.async.wait_group %0;" :: "n"(N) : "memory");
}

// ---------------- prep: split inputs + weights --------------------------------
__global__ void __launch_bounds__(256) split_all(
    const float* __restrict__ q, const float* __restrict__ k, const float* __restrict__ v,
    const float* __restrict__ wq, const float* __restrict__ wk,
    const float* __restrict__ wv, const float* __restrict__ wc)
{
    int i = blockIdx.x * 256 + threadIdx.x;          // float4 index
    const float* src;
    __nv_bfloat16 *dh, *dl;
    int off;
    if (i < 3 * 1048576) {
        int ti = i >> 20; off = i & 1048575;
        src = (ti == 0) ? q : (ti == 1) ? k : v;
        dh = g_xs_h[ti]; dl = g_xs_l[ti];
    } else {
        int j = i - 3145728;
        int ti = j >> 18; off = j & 262143;
        src = (ti == 0) ? wq : (ti == 1) ? wk : (ti == 2) ? wv : wc;
        dh = g_ws_h[ti]; dl = g_ws_l[ti];
    }
    float4 x = ((const float4*)src)[off];
    uint32_t h01, l01, h23, l23;
    split2(x.x, x.y, h01, l01);
    split2(x.z, x.w, h23, l23);
    ((uint2*)dh)[off] = make_uint2(h01, h23);
    ((uint2*)dl)[off] = make_uint2(l01, l23);
}

// ---------------- projection GEMM (chunk 64, 3-stage, 1 CTA/SM) ---------------
// mode 0 pre-scales the output by 0.125 (softmax scale folded into Q; exact).
__global__ void __launch_bounds__(256, 1)
proj_tc(const float* __restrict__ bq, const float* __restrict__ bk,
        const float* __restrict__ bv, const float* __restrict__ bc,
        float* __restrict__ Yout, int mode_base)
{
    extern __shared__ __align__(1024) char smp[];
    uint32_t sb = smem_u32(smp);
    const int t = threadIdx.x, lane = t & 31, wid = t >> 5;
    const int wy = wid >> 2, wx = wid & 3;
    const int mode = mode_base + blockIdx.z;
    const __nv_bfloat16 *Xh, *Xl;
    if (mode < 3) { Xh = g_xs_h[mode]; Xl = g_xs_l[mode]; }
    else          { Xh = g_cat_h;      Xl = g_cat_l; }
    const __nv_bfloat16 *Wh = g_ws_h[mode], *Wl = g_ws_l[mode];
    const float* bias = (mode == 0) ? bq : (mode == 1) ? bk : (mode == 2) ? bv : bc;
    const int bm = blockIdx.y * 128, bn = blockIdx.x * 128;

    float acc[4][4][4];
#pragma unroll
    for (int i = 0; i < 4; i++)
#pragma unroll
        for (int j = 0; j < 4; j++)
#pragma unroll
            for (int k = 0; k < 4; k++) acc[i][j][k] = 0.0f;

#define PJ_PF(c) do { \
    const int kc_ = (c) * 64; \
    uint32_t bo_ = sb + ((c) % 3) * 65536; \
    _Pragma("unroll") \
    for (int i_ = 0; i_ < 4; i_++) { \
        int e_ = i_ * 256 + t, r_ = e_ >> 3, c8_ = e_ & 7; \
        uint32_t so_ = r_ * 128 + ((c8_ ^ (r_ & 7)) << 4); \
        const size_t g_ = (size_t)(bm + r_) * D_ + kc_ + c8_ * 8; \
        cp16(bo_ + so_,         Xh + g_); \
        cp16(bo_ + 16384 + so_, Xl + g_); \
    } \
    _Pragma("unroll") \
    for (int i_ = 0; i_ < 4; i_++) { \
        int e_ = i_ * 256 + t, k_ = e_ >> 4, b_ = e_ & 15; \
        uint32_t so_ = k_ * 256 + ((b_ ^ (k_ & 7)) << 4); \
        const size_t g_ = (size_t)(kc_ + k_) * D_ + bn + b_ * 8; \
        cp16(bo_ + 32768 + so_, Wh + g_); \
        cp16(bo_ + 49152 + so_, Wl + g_); \
    } \
    CP_COMMIT(); \
} while (0)

#define PJ_MMA(base) do { \
    uint32_t aAH = (base), aAL = (base) + 16384, aBH = (base) + 32768, aBL = (base) + 49152; \
    _Pragma("unroll") \
    for (int s = 0; s < 4; s++) { \
        const int rA0 = wy * 64 + ((lane >> 3) & 1) * 8 + (lane & 7); \
        const int cA = 2 * s + (lane >> 4); \
        uint32_t ah[4][4], al[4][4]; \
        _Pragma("unroll") \
        for (int mi = 0; mi < 4; mi++) { \
            int r = rA0 + mi * 16; \
            uint32_t off = r * 128 + ((cA ^ (r & 7)) << 4); \
            ldsm4(ah[mi], aAH + off); \
            ldsm4(al[mi], aAL + off); \
        } \
        const int rB = 16 * s + ((lane >> 3) & 1) * 8 + (lane & 7); \
        uint32_t bh[2][4], bl[2][4]; \
        _Pragma("unroll") \
        for (int nh = 0; nh < 2; nh++) { \
            int cB = ((wx * 32 + nh * 16) >> 3) + ((lane >> 4) & 1); \
            uint32_t off = rB * 256 + ((cB ^ (rB & 7)) << 4); \
            ldsm4t(bh[nh], aBH + off); \
            ldsm4t(bl[nh], aBL + off); \
        } \
        _Pragma("unroll") \
        for (int mi = 0; mi < 4; mi++) \
            _Pragma("unroll") \
            for (int nj = 0; nj < 4; nj++) { \
                uint32_t bh0 = bh[nj >> 1][(nj & 1) * 2], bh1 = bh[nj >> 1][(nj & 1) * 2 + 1]; \
                uint32_t bl0 = bl[nj >> 1][(nj & 1) * 2], bl1 = bl[nj >> 1][(nj & 1) * 2 + 1]; \
                mma_bf16(acc[mi][nj], ah[mi], bh0, bh1); \
                mma_bf16(acc[mi][nj], ah[mi], bl0, bl1); \
                mma_bf16(acc[mi][nj], al[mi], bh0, bh1); \
            } \
    } \
} while (0)

    PJ_PF(0); PJ_PF(1);
#pragma unroll 1
    for (int c = 0; c < 16; c++) {
        if (c + 2 < 16) PJ_PF(c + 2);
        if (c < 14) cp_wait<2>(); else if (c == 14) cp_wait<1>(); else cp_wait<0>();
        __syncthreads();
        PJ_MMA(sb + (c % 3) * 65536);
        __syncthreads();
    }

    const int er = lane >> 2, ec = (lane & 3) * 2;
    if (mode < 3) {
        const float sc = (mode == 0) ? 0.125f : 1.0f;   // fold softmax scale into Q (exact)
        __nv_bfloat16* dh = g_hd_h[mode];
        __nv_bfloat16* dl = g_hd_l[mode];
#pragma unroll
        for (int mi = 0; mi < 4; mi++)
#pragma unroll
            for (int nj = 0; nj < 4; nj++) {
                const int col = bn + wx * 32 + nj * 8 + ec;
                const float b0 = __ldg(bias + col), b1 = __ldg(bias + col + 1);
                const int row0 = bm + wy * 64 + mi * 16 + er;
#pragma unroll
                for (int h = 0; h < 2; h++) {
                    const int row = row0 + h * 8;
                    uint32_t hv, lv;
                    split2((acc[mi][nj][h * 2] + b0) * sc, (acc[mi][nj][h * 2 + 1] + b1) * sc, hv, lv);
                    int bb = row >> 11, ss = row & (S_ - 1), hh = col >> 6, dd = col & (DH_ - 1);
                    size_t idx = (((size_t)(bb * H_ + hh)) * S_ + ss) * DH_ + dd;
                    *(uint32_t*)(dh + idx) = hv;
                    *(uint32_t*)(dl + idx) = lv;
                }
            }
    } else {
#pragma unroll
        for (int mi = 0; mi < 4; mi++)
#pragma unroll
            for (int nj = 0; nj < 4; nj++) {
                const int col = bn + wx * 32 + nj * 8 + ec;
                const float b0 = __ldg(bias + col), b1 = __ldg(bias + col + 1);
                const int row0 = bm + wy * 64 + mi * 16 + er;
#pragma unroll
                for (int h = 0; h < 2; h++) {
                    float2 v = make_float2(acc[mi][nj][h * 2] + b0, acc[mi][nj][h * 2 + 1] + b1);
                    *(float2*)(Yout + (size_t)(row0 + h * 8) * D_ + col) = v;
                }
            }
    }
}

// ---------------- fused attention (2-pass, merged stats; Q pre-scaled) --------
// SMEM (96KB):
//  pass1: Q @0 (hi 16K, lo 16K); K buf0 @32K, K buf1 @64K (hi 16K, lo 16K each)
//  pass2: P buf0 @0, P buf1 @32K (hi 16K, lo 16K); V buf0 @64K (hi 8K, lo 8K), buf1 @80K
__global__ void __launch_bounds__(256, 2) fused_attn(float* __restrict__ attn)
{
    extern __shared__ __align__(1024) char smp[];
    __shared__ float2 s_red[128][4];      // (max, sumexp) partials per wx
    __shared__ float sm_m[128], sm_s[128], sm_i[128];
    uint32_t sb = smem_u32(smp);
    const int t = threadIdx.x, lane = t & 31, wid = t >> 5;
    const int bh = blockIdx.y, q0 = blockIdx.x * 128;
    const __nv_bfloat16* Qh = g_hd_h[0] + (size_t)bh * S_ * DH_;
    const __nv_bfloat16* Ql = g_hd_l[0] + (size_t)bh * S_ * DH_;
    const __nv_bfloat16* Kh = g_hd_h[1] + (size_t)bh * S_ * DH_;
    const __nv_bfloat16* Kl = g_hd_l[1] + (size_t)bh * S_ * DH_;
    const __nv_bfloat16* Vh = g_hd_h[2] + (size_t)bh * S_ * DH_;
    const __nv_bfloat16* Vl = g_hd_l[2] + (size_t)bh * S_ * DH_;
    float* A = attn + (size_t)bh * S_ * S_;

    if (t < 128) { sm_m[t] = -1e30f; sm_s[t] = 0.0f; }

    // ---- load Q (group with K0) ----
#pragma unroll
    for (int i = 0; i < 4; i++) {
        int e = i * 256 + t, r = e >> 3, c8 = e & 7;
        uint32_t so = r * 128 + ((c8 ^ (r & 7)) << 4);
        cp16(sb + so,         Qh + (size_t)(q0 + r) * DH_ + c8 * 8);
        cp16(sb + 16384 + so, Ql + (size_t)(q0 + r) * DH_ + c8 * 8);
    }
#define FA_KPF(kt) do { \
    uint32_t kb_ = sb + 32768 + ((kt) & 1) * 32768; \
    _Pragma("unroll") \
    for (int i_ = 0; i_ < 4; i_++) { \
        int e_ = i_ * 256 + t, r_ = e_ >> 3, c8_ = e_ & 7; \
        uint32_t so_ = r_ * 128 + ((c8_ ^ (r_ & 7)) << 4); \
        cp16(kb_ + so_,         Kh + (size_t)((kt) * 128 + r_) * DH_ + c8_ * 8); \
        cp16(kb_ + 16384 + so_, Kl + (size_t)((kt) * 128 + r_) * DH_ + c8_ * 8); \
    } \
    CP_COMMIT(); \
} while (0)

    FA_KPF(0);          // group0 = Q + K0
    FA_KPF(1);          // group1 = K1

    // ================= PASS 1: S = Qs K^T (Q pre-scaled), online stats =========
    {
        const int wy = wid >> 2, wx = wid & 3;       // 2 x 4 warps, warp 64q x 32k
        const int er = lane >> 2, ec = (lane & 3) * 2;
#pragma unroll 1
        for (int kt = 0; kt < 16; kt++) {
            if (kt == 15) cp_wait<0>(); else cp_wait<1>();
            __syncthreads();                          // also protects s_red reuse

            float acc[4][4][4];
#pragma unroll
            for (int i = 0; i < 4; i++)
#pragma unroll
                for (int j = 0; j < 4; j++)
#pragma unroll
                    for (int k = 0; k < 4; k++) acc[i][j][k] = 0.0f;

            const uint32_t aQH = sb, aQL = sb + 16384;
            const uint32_t aKH = sb + 32768 + (kt & 1) * 32768, aKL = aKH + 16384;
#pragma unroll
            for (int s = 0; s < 4; s++) {
                const int rA0 = wy * 64 + ((lane >> 3) & 1) * 8 + (lane & 7);
                const int cA = 2 * s + (lane >> 4);
                uint32_t ah[4][4], al[4][4];
#pragma unroll
                for (int mi = 0; mi < 4; mi++) {
                    int r = rA0 + mi * 16;
                    uint32_t off = r * 128 + ((cA ^ (r & 7)) << 4);
                    ldsm4(ah[mi], aQH + off);
                    ldsm4(al[mi], aQL + off);
                }
                uint32_t bhf[2][4], blf[2][4];
                const int cB = 2 * s + ((lane >> 3) & 1);
#pragma unroll
                for (int nh = 0; nh < 2; nh++) {
                    int r = wx * 32 + nh * 16 + ((lane >> 4) & 1) * 8 + (lane & 7);
                    uint32_t off = r * 128 + ((cB ^ (r & 7)) << 4);
                    ldsm4(bhf[nh], aKH + off);
                    ldsm4(blf[nh], aKL + off);
                }
#pragma unroll
                for (int mi = 0; mi < 4; mi++)
#pragma unroll
                    for (int nj = 0; nj < 4; nj++) {
                        uint32_t b0 = bhf[nj >> 1][(nj & 1) * 2], b1 = bhf[nj >> 1][(nj & 1) * 2 + 1];
                        uint32_t c0 = blf[nj >> 1][(nj & 1) * 2], c1 = blf[nj >> 1][(nj & 1) * 2 + 1];
                        mma_bf16(acc[mi][nj], ah[mi], b0, b1);
                        mma_bf16(acc[mi][nj], ah[mi], c0, c1);
                        mma_bf16(acc[mi][nj], al[mi], b0, b1);
                    }
            }

            // warp-local (max, sumexp) partials — one pass, one sync
#pragma unroll
            for (int mi = 0; mi < 4; mi++)
#pragma unroll
                for (int h = 0; h < 2; h++) {
                    float m = -1e30f;
#pragma unroll
                    for (int nj = 0; nj < 4; nj++)
                        m = fmaxf(m, fmaxf(acc[mi][nj][h * 2], acc[mi][nj][h * 2 + 1]));
                    m = fmaxf(m, __shfl_xor_sync(0xffffffffu, m, 1));
                    m = fmaxf(m, __shfl_xor_sync(0xffffffffu, m, 2));
                    float s = 0.0f;
#pragma unroll
                    for (int nj = 0; nj < 4; nj++)
                        s += __expf(acc[mi][nj][h * 2] - m) + __expf(acc[mi][nj][h * 2 + 1] - m);
                    s += __shfl_xor_sync(0xffffffffu, s, 1);
                    s += __shfl_xor_sync(0xffffffffu, s, 2);
                    if ((lane & 3) == 0)
                        s_red[wy * 64 + mi * 16 + h * 8 + er][wx] = make_float2(m, s);
                }
            __syncthreads();
            if (t < 128) {
                float2 p0 = s_red[t][0], p1 = s_red[t][1], p2 = s_red[t][2], p3 = s_red[t][3];
                float mt = fmaxf(fmaxf(p0.x, p1.x), fmaxf(p2.x, p3.x));
                float st = p0.y * __expf(p0.x - mt) + p1.y * __expf(p1.x - mt)
                         + p2.y * __expf(p2.x - mt) + p3.y * __expf(p3.x - mt);
                float mo = sm_m[t];
                float mn = fmaxf(mo, mt);
                sm_s[t] = sm_s[t] * __expf(mo - mn) + st * __expf(mt - mn);
                sm_m[t] = mn;
            }
            // write raw S tile (already softmax-scaled via Q)
            const int k0 = kt * 128;
#pragma unroll
            for (int mi = 0; mi < 4; mi++)
#pragma unroll
                for (int nj = 0; nj < 4; nj++) {
                    const int col = k0 + wx * 32 + nj * 8 + ec;
                    const int row0 = q0 + wy * 64 + mi * 16 + er;
#pragma unroll
                    for (int h = 0; h < 2; h++) {
                        float2 v = make_float2(acc[mi][nj][h * 2], acc[mi][nj][h * 2 + 1]);
                        *(float2*)(A + (size_t)(row0 + h * 8) * S_ + col) = v;
                    }
                }
            if (kt + 2 < 16) FA_KPF(kt + 2);
        }
    }
    __syncthreads();
    if (t < 128) sm_i[t] = 1.0f / sm_s[t];
    __syncthreads();

    // ================= PASS 2: p = exp(S-m)*inv ; O = p @ V ====================
    {
        const int wy = wid >> 1, wx = wid & 1;       // 4 x 2 warps, warp 32q x 32d
        float acc[2][4][4];
#pragma unroll
        for (int i = 0; i < 2; i++)
#pragma unroll
            for (int j = 0; j < 4; j++)
#pragma unroll
                for (int k = 0; k < 4; k++) acc[i][j][k] = 0.0f;

        float4 ra[8];
        const int arow = t >> 4, ac4 = t & 15;

#define FA_VPF(c) do { \
    const int kc_ = (c) * 64; \
    uint32_t vb_ = sb + 65536 + ((c) & 1) * 16384; \
    _Pragma("unroll") \
    for (int i_ = 0; i_ < 2; i_++) { \
        int e_ = i_ * 256 + t, r_ = e_ >> 3, c8_ = e_ & 7; \
        uint32_t so_ = r_ * 128 + ((c8_ ^ (r_ & 7)) << 4); \
        cp16(vb_ + so_,        Vh + (size_t)(kc_ + r_) * DH_ + c8_ * 8); \
        cp16(vb_ + 8192 + so_, Vl + (size_t)(kc_ + r_) * DH_ + c8_ * 8); \
    } \
    CP_COMMIT(); \
} while (0)

#define FA_LDA(c) do { \
    const int kc_ = (c) * 64; \
    _Pragma("unroll") \
    for (int i_ = 0; i_ < 8; i_++) \
        ra[i_] = *(const float4*)(A + (size_t)(q0 + i_ * 16 + arow) * S_ + kc_ + ac4 * 4); \
} while (0)

#define FA_STA(c) do { \
    const int kc_ = (c) * 64; \
    char* ab_ = smp + ((c) & 1) * 32768; \
    _Pragma("unroll") \
    for (int i_ = 0; i_ < 8; i_++) { \
        int r_ = i_ * 16 + arow; \
        const float m_ = sm_m[r_], in_ = sm_i[r_]; \
        float4 p_; \
        p_.x = __expf(ra[i_].x - m_) * in_; \
        p_.y = __expf(ra[i_].y - m_) * in_; \
        p_.z = __expf(ra[i_].z - m_) * in_; \
        p_.w = __expf(ra[i_].w - m_) * in_; \
        *(float4*)(A + (size_t)(q0 + r_) * S_ + kc_ + ac4 * 4) = p_; \
        uint32_t h01, l01, h23, l23; \
        split2(p_.x, p_.y, h01, l01); \
        split2(p_.z, p_.w, h23, l23); \
        uint32_t so_ = r_ * 128 + ((((ac4 >> 1) ^ (r_ & 7)) << 4)) + (ac4 & 1) * 8; \
        *(uint2*)(ab_ + so_)         = make_uint2(h01, h23); \
        *(uint2*)(ab_ + 16384 + so_) = make_uint2(l01, l23); \
    } \
} while (0)

#define FA_MMA(c) do { \
    uint32_t aAH = sb + ((c) & 1) * 32768, aAL = aAH + 16384; \
    uint32_t aBH = sb + 65536 + ((c) & 1) * 16384, aBL = aBH + 8192; \
    _Pragma("unroll") \
    for (int s = 0; s < 4; s++) { \
        const int rA0 = wy * 32 + ((lane >> 3) & 1) * 8 + (lane & 7); \
        const int cA = 2 * s + (lane >> 4); \
        uint32_t ah[2][4], al[2][4]; \
        _Pragma("unroll") \
        for (int mi = 0; mi < 2; mi++) { \
            int r = rA0 + mi * 16; \
            uint32_t off = r * 128 + ((cA ^ (r & 7)) << 4); \
            ldsm4(ah[mi], aAH + off); \
            ldsm4(al[mi], aAL + off); \
        } \
        const int rB = 16 * s + ((lane >> 3) & 1) * 8 + (lane & 7); \
        uint32_t bh2[2][4], bl2[2][4]; \
        _Pragma("unroll") \
        for (int nh = 0; nh < 2; nh++) { \
            int cB = ((wx * 32 + nh * 16) >> 3) + ((lane >> 4) & 1); \
            uint32_t off = rB * 128 + ((cB ^ (rB & 7)) << 4); \
            ldsm4t(bh2[nh], aBH + off); \
            ldsm4t(bl2[nh], aBL + off); \
        } \
        _Pragma("unroll") \
        for (int mi = 0; mi < 2; mi++) \
            _Pragma("unroll") \
            for (int nj = 0; nj < 4; nj++) { \
                uint32_t b0 = bh2[nj >> 1][(nj & 1) * 2], b1 = bh2[nj >> 1][(nj & 1) * 2 + 1]; \
                uint32_t c0 = bl2[nj >> 1][(nj & 1) * 2], c1 = bl2[nj >> 1][(nj & 1) * 2 + 1]; \
                mma_bf16(acc[mi][nj], ah[mi], b0, b1); \
                mma_bf16(acc[mi][nj], ah[mi], c0, c1); \
                mma_bf16(acc[mi][nj], al[mi], b0, b1); \
            } \
    } \
} while (0)

        // reverse order: most recently written S tiles are read first (L2 warm)
        FA_VPF(31);
        FA_LDA(31);
        FA_STA(31);
#pragma unroll 1
        for (int c = 31; c >= 0; c--) {
            if (c > 0) { FA_VPF(c - 1); FA_LDA(c - 1); }
            if (c > 0) cp_wait<1>(); else cp_wait<0>();
            __syncthreads();
            FA_MMA(c);
            if (c > 0) FA_STA(c - 1);
            __syncthreads();
        }

        const int bb = bh >> 4, hh = bh & (H_ - 1);
        const int er = lane >> 2, ec = (lane & 3) * 2;
#pragma unroll
        for (int mi = 0; mi < 2; mi++)
#pragma unroll
            for (int nj = 0; nj < 4; nj++) {
                const int dd = wx * 32 + nj * 8 + ec;
                const int row0 = q0 + wy * 32 + mi * 16 + er;
#pragma unroll
                for (int h = 0; h < 2; h++) {
                    const int ss = row0 + h * 8;
                    uint32_t hv, lv;
                    split2(acc[mi][nj][h * 2], acc[mi][nj][h * 2 + 1], hv, lv);
                    size_t idx = ((size_t)(bb * S_ + ss)) * D_ + hh * DH_ + dd;
                    *(uint32_t*)(g_cat_h + idx) = hv;
                    *(uint32_t*)(g_cat_l + idx) = lv;
                }
            }
    }
}

// ---------------- launch ------------------------------------------------------
extern "C" void kernel_launch(void* const* d_in, const int* in_sizes, int n_in,
                              void* d_out, int out_size)
{
    const float* q  = (const float*)d_in[0];
    const float* k  = (const float*)d_in[1];
    const float* v  = (const float*)d_in[2];
    const float* Wq = (const float*)d_in[3];
    const float* bq = (const float*)d_in[4];
    const float* Wk = (const float*)d_in[5];
    const float* bk = (const float*)d_in[6];
    const float* Wv = (const float*)d_in[7];
    const float* bv = (const float*)d_in[8];
    const float* Wc = (const float*)d_in[9];
    const float* bc = (const float*)d_in[10];

    float* out  = (float*)d_out;
    float* attn = out + OUT_ELEMS;

    const int SM_PROJ = 196608;
    const int SM_FA   = 98304;
    cudaFuncSetAttribute(proj_tc,    cudaFuncAttributeMaxDynamicSharedMemorySize, SM_PROJ);
    cudaFuncSetAttribute(fused_attn, cudaFuncAttributeMaxDynamicSharedMemorySize, SM_FA);

    split_all<<<16384, 256>>>(q, k, v, Wq, Wk, Wv, Wc);

    proj_tc<<<dim3(8, 32, 3), 256, SM_PROJ>>>(bq, bk, bv, bc, nullptr, 0);

    fused_attn<<<dim3(16, 32), 256, SM_FA>>>(attn);

    proj_tc<<<dim3(8, 32, 1), 256, SM_PROJ>>>(bq, bk, bv, bc, out, 3);
}

// round 13
// speedup vs baseline: 1.5269x; 1.0139x over previous
#include <cuda_runtime.h>
#include <cuda_bf16.h>
#include <math.h>
#include <stdint.h>

#define B_ 2
#define S_ 2048
#define D_ 1024
#define H_ 16
#define DH_ 64
#define NTOK 4096
#define OUT_ELEMS ((size_t)NTOK * D_)

// ---------------- pre-split bf16 hi/lo scratch -------------------------------
__device__ __nv_bfloat16 g_xs_h[3][(size_t)NTOK * D_];
__device__ __nv_bfloat16 g_xs_l[3][(size_t)NTOK * D_];
__device__ __nv_bfloat16 g_ws_h[4][(size_t)D_ * D_];
__device__ __nv_bfloat16 g_ws_l[4][(size_t)D_ * D_];
__device__ __nv_bfloat16 g_hd_h[3][(size_t)NTOK * D_];   // head-split q/k/v (q pre-scaled 0.125)
__device__ __nv_bfloat16 g_hd_l[3][(size_t)NTOK * D_];
__device__ __nv_bfloat16 g_cat_h[(size_t)NTOK * D_];
__device__ __nv_bfloat16 g_cat_l[(size_t)NTOK * D_];

// ---------------- helpers -----------------------------------------------------
__device__ __forceinline__ uint32_t smem_u32(const void* p) {
    uint32_t a;
    asm("{ .reg .u64 t; cvta.to.shared.u64 t, %1; cvt.u32.u64 %0, t; }" : "=r"(a) : "l"(p));
    return a;
}
__device__ __forceinline__ void mma_bf16(float c[4], const uint32_t a[4],
                                         uint32_t b0, uint32_t b1) {
    asm volatile("mma.sync.aligned.m16n8k16.row.col.f32.bf16.bf16.f32 "
        "{%0,%1,%2,%3}, {%4,%5,%6,%7}, {%8,%9}, {%0,%1,%2,%3};"
        : "+f"(c[0]), "+f"(c[1]), "+f"(c[2]), "+f"(c[3])
        : "r"(a[0]), "r"(a[1]), "r"(a[2]), "r"(a[3]), "r"(b0), "r"(b1));
}
__device__ __forceinline__ void ldsm4(uint32_t r[4], uint32_t a) {
    asm volatile("ldmatrix.sync.aligned.m8n8.x4.shared.b16 {%0,%1,%2,%3}, [%4];"
        : "=r"(r[0]), "=r"(r[1]), "=r"(r[2]), "=r"(r[3]) : "r"(a));
}
__device__ __forceinline__ void ldsm4t(uint32_t r[4], uint32_t a) {
    asm volatile("ldmatrix.sync.aligned.m8n8.x4.trans.shared.b16 {%0,%1,%2,%3}, [%4];"
        : "=r"(r[0]), "=r"(r[1]), "=r"(r[2]), "=r"(r[3]) : "r"(a));
}
__device__ __forceinline__ void split2(float x, float y, uint32_t& hi, uint32_t& lo) {
    __nv_bfloat16 hx = __float2bfloat16(x), hy = __float2bfloat16(y);
    __nv_bfloat16 lx = __float2bfloat16(x - __bfloat162float(hx));
    __nv_bfloat16 ly = __float2bfloat16(y - __bfloat162float(hy));
    __nv_bfloat162 h(hx, hy), l(lx, ly);
    hi = *(uint32_t*)&h;
    lo = *(uint32_t*)&l;
}
__device__ __forceinline__ void cp16(uint32_t smem, const void* g) {
    asm volatile("cp.async.cg.shared.global [%0], [%1], 16;" :: "r"(smem), "l"(g));
}
#define CP_COMMIT() asm volatile("cp.async.commit_group;" ::: "memory")
template<int N> __device__ __forceinline__ void cp_wait() {
    asm volatile("cp.async.wait_group %0;" :: "n"(N) : "memory");
}

// ---------------- prep: split inputs + weights --------------------------------
__global__ void __launch_bounds__(256) split_all(
    const float* __restrict__ q, const float* __restrict__ k, const float* __restrict__ v,
    const float* __restrict__ wq, const float* __restrict__ wk,
    const float* __restrict__ wv, const float* __restrict__ wc)
{
    int i = blockIdx.x * 256 + threadIdx.x;          // float4 index
    const float* src;
    __nv_bfloat16 *dh, *dl;
    int off;
    if (i < 3 * 1048576) {
        int ti = i >> 20; off = i & 1048575;
        src = (ti == 0) ? q : (ti == 1) ? k : v;
        dh = g_xs_h[ti]; dl = g_xs_l[ti];
    } else {
        int j = i - 3145728;
        int ti = j >> 18; off = j & 262143;
        src = (ti == 0) ? wq : (ti == 1) ? wk : (ti == 2) ? wv : wc;
        dh = g_ws_h[ti]; dl = g_ws_l[ti];
    }
    float4 x = ((const float4*)src)[off];
    uint32_t h01, l01, h23, l23;
    split2(x.x, x.y, h01, l01);
    split2(x.z, x.w, h23, l23);
    ((uint2*)dh)[off] = make_uint2(h01, h23);
    ((uint2*)dl)[off] = make_uint2(l01, l23);
}

// ---------------- projection GEMM (chunk 64, 3-stage, 1 CTA/SM) ---------------
// mode 0 pre-scales the output by 0.125 (softmax scale folded into Q; exact).
__global__ void __launch_bounds__(256, 1)
proj_tc(const float* __restrict__ bq, const float* __restrict__ bk,
        const float* __restrict__ bv, const float* __restrict__ bc,
        float* __restrict__ Yout, int mode_base)
{
    extern __shared__ __align__(1024) char smp[];
    uint32_t sb = smem_u32(smp);
    const int t = threadIdx.x, lane = t & 31, wid = t >> 5;
    const int wy = wid >> 2, wx = wid & 3;
    const int mode = mode_base + blockIdx.z;
    const __nv_bfloat16 *Xh, *Xl;
    if (mode < 3) { Xh = g_xs_h[mode]; Xl = g_xs_l[mode]; }
    else          { Xh = g_cat_h;      Xl = g_cat_l; }
    const __nv_bfloat16 *Wh = g_ws_h[mode], *Wl = g_ws_l[mode];
    const float* bias = (mode == 0) ? bq : (mode == 1) ? bk : (mode == 2) ? bv : bc;
    const int bm = blockIdx.y * 128, bn = blockIdx.x * 128;

    float acc[4][4][4];
#pragma unroll
    for (int i = 0; i < 4; i++)
#pragma unroll
        for (int j = 0; j < 4; j++)
#pragma unroll
            for (int k = 0; k < 4; k++) acc[i][j][k] = 0.0f;

#define PJ_PF(c) do { \
    const int kc_ = (c) * 64; \
    uint32_t bo_ = sb + ((c) % 3) * 65536; \
    _Pragma("unroll") \
    for (int i_ = 0; i_ < 4; i_++) { \
        int e_ = i_ * 256 + t, r_ = e_ >> 3, c8_ = e_ & 7; \
        uint32_t so_ = r_ * 128 + ((c8_ ^ (r_ & 7)) << 4); \
        const size_t g_ = (size_t)(bm + r_) * D_ + kc_ + c8_ * 8; \
        cp16(bo_ + so_,         Xh + g_); \
        cp16(bo_ + 16384 + so_, Xl + g_); \
    } \
    _Pragma("unroll") \
    for (int i_ = 0; i_ < 4; i_++) { \
        int e_ = i_ * 256 + t, k_ = e_ >> 4, b_ = e_ & 15; \
        uint32_t so_ = k_ * 256 + ((b_ ^ (k_ & 7)) << 4); \
        const size_t g_ = (size_t)(kc_ + k_) * D_ + bn + b_ * 8; \
        cp16(bo_ + 32768 + so_, Wh + g_); \
        cp16(bo_ + 49152 + so_, Wl + g_); \
    } \
    CP_COMMIT(); \
} while (0)

#define PJ_MMA(base) do { \
    uint32_t aAH = (base), aAL = (base) + 16384, aBH = (base) + 32768, aBL = (base) + 49152; \
    _Pragma("unroll") \
    for (int s = 0; s < 4; s++) { \
        const int rA0 = wy * 64 + ((lane >> 3) & 1) * 8 + (lane & 7); \
        const int cA = 2 * s + (lane >> 4); \
        uint32_t ah[4][4], al[4][4]; \
        _Pragma("unroll") \
        for (int mi = 0; mi < 4; mi++) { \
            int r = rA0 + mi * 16; \
            uint32_t off = r * 128 + ((cA ^ (r & 7)) << 4); \
            ldsm4(ah[mi], aAH + off); \
            ldsm4(al[mi], aAL + off); \
        } \
        const int rB = 16 * s + ((lane >> 3) & 1) * 8 + (lane & 7); \
        uint32_t bh[2][4], bl[2][4]; \
        _Pragma("unroll") \
        for (int nh = 0; nh < 2; nh++) { \
            int cB = ((wx * 32 + nh * 16) >> 3) + ((lane >> 4) & 1); \
            uint32_t off = rB * 256 + ((cB ^ (rB & 7)) << 4); \
            ldsm4t(bh[nh], aBH + off); \
            ldsm4t(bl[nh], aBL + off); \
        } \
        _Pragma("unroll") \
        for (int mi = 0; mi < 4; mi++) \
            _Pragma("unroll") \
            for (int nj = 0; nj < 4; nj++) { \
                uint32_t bh0 = bh[nj >> 1][(nj & 1) * 2], bh1 = bh[nj >> 1][(nj & 1) * 2 + 1]; \
                uint32_t bl0 = bl[nj >> 1][(nj & 1) * 2], bl1 = bl[nj >> 1][(nj & 1) * 2 + 1]; \
                mma_bf16(acc[mi][nj], ah[mi], bh0, bh1); \
                mma_bf16(acc[mi][nj], ah[mi], bl0, bl1); \
                mma_bf16(acc[mi][nj], al[mi], bh0, bh1); \
            } \
    } \
} while (0)

    PJ_PF(0); PJ_PF(1);
#pragma unroll 1
    for (int c = 0; c < 16; c++) {
        if (c + 2 < 16) PJ_PF(c + 2);
        if (c < 14) cp_wait<2>(); else if (c == 14) cp_wait<1>(); else cp_wait<0>();
        __syncthreads();
        PJ_MMA(sb + (c % 3) * 65536);
        __syncthreads();
    }

    const int er = lane >> 2, ec = (lane & 3) * 2;
    if (mode < 3) {
        const float sc = (mode == 0) ? 0.125f : 1.0f;   // fold softmax scale into Q (exact)
        __nv_bfloat16* dh = g_hd_h[mode];
        __nv_bfloat16* dl = g_hd_l[mode];
#pragma unroll
        for (int mi = 0; mi < 4; mi++)
#pragma unroll
            for (int nj = 0; nj < 4; nj++) {
                const int col = bn + wx * 32 + nj * 8 + ec;
                const float b0 = __ldg(bias + col), b1 = __ldg(bias + col + 1);
                const int row0 = bm + wy * 64 + mi * 16 + er;
#pragma unroll
                for (int h = 0; h < 2; h++) {
                    const int row = row0 + h * 8;
                    uint32_t hv, lv;
                    split2((acc[mi][nj][h * 2] + b0) * sc, (acc[mi][nj][h * 2 + 1] + b1) * sc, hv, lv);
                    int bb = row >> 11, ss = row & (S_ - 1), hh = col >> 6, dd = col & (DH_ - 1);
                    size_t idx = (((size_t)(bb * H_ + hh)) * S_ + ss) * DH_ + dd;
                    *(uint32_t*)(dh + idx) = hv;
                    *(uint32_t*)(dl + idx) = lv;
                }
            }
    } else {
#pragma unroll
        for (int mi = 0; mi < 4; mi++)
#pragma unroll
            for (int nj = 0; nj < 4; nj++) {
                const int col = bn + wx * 32 + nj * 8 + ec;
                const float b0 = __ldg(bias + col), b1 = __ldg(bias + col + 1);
                const int row0 = bm + wy * 64 + mi * 16 + er;
#pragma unroll
                for (int h = 0; h < 2; h++) {
                    float2 v = make_float2(acc[mi][nj][h * 2] + b0, acc[mi][nj][h * 2 + 1] + b1);
                    *(float2*)(Yout + (size_t)(row0 + h * 8) * D_ + col) = v;
                }
            }
    }
}

// ---------------- fused attention: pass1 stats-only, pass2 flash --------------
// SMEM (96KB):
//  Q @0 (hi 16K, lo 16K)                                   [persistent, both passes]
//  pass1: K tiles 128 rows: buf0 @32K, buf1 @64K (hi 16K, lo 16K each)
//  pass2: K bufs @32K,@48K (hi 8K, lo 8K); V bufs @64K,@80K (hi 8K, lo 8K)
__global__ void __launch_bounds__(256, 2) fused_attn(float* __restrict__ attn)
{
    extern __shared__ __align__(1024) char smp[];
    __shared__ float2 s_red[128][4];
    __shared__ float sm_m[128], sm_s[128], sm_i[128];
    uint32_t sb = smem_u32(smp);
    const int t = threadIdx.x, lane = t & 31, wid = t >> 5;
    const int bh = blockIdx.y, q0 = blockIdx.x * 128;
    const __nv_bfloat16* Qh = g_hd_h[0] + (size_t)bh * S_ * DH_;
    const __nv_bfloat16* Ql = g_hd_l[0] + (size_t)bh * S_ * DH_;
    const __nv_bfloat16* Kh = g_hd_h[1] + (size_t)bh * S_ * DH_;
    const __nv_bfloat16* Kl = g_hd_l[1] + (size_t)bh * S_ * DH_;
    const __nv_bfloat16* Vh = g_hd_h[2] + (size_t)bh * S_ * DH_;
    const __nv_bfloat16* Vl = g_hd_l[2] + (size_t)bh * S_ * DH_;
    float* A = attn + (size_t)bh * S_ * S_;

    if (t < 128) { sm_m[t] = -1e30f; sm_s[t] = 0.0f; }

    // ---- load Q (group with K0) ----
#pragma unroll
    for (int i = 0; i < 4; i++) {
        int e = i * 256 + t, r = e >> 3, c8 = e & 7;
        uint32_t so = r * 128 + ((c8 ^ (r & 7)) << 4);
        cp16(sb + so,         Qh + (size_t)(q0 + r) * DH_ + c8 * 8);
        cp16(sb + 16384 + so, Ql + (size_t)(q0 + r) * DH_ + c8 * 8);
    }
#define FA_KPF(kt) do { \
    uint32_t kb_ = sb + 32768 + ((kt) & 1) * 32768; \
    _Pragma("unroll") \
    for (int i_ = 0; i_ < 4; i_++) { \
        int e_ = i_ * 256 + t, r_ = e_ >> 3, c8_ = e_ & 7; \
        uint32_t so_ = r_ * 128 + ((c8_ ^ (r_ & 7)) << 4); \
        cp16(kb_ + so_,         Kh + (size_t)((kt) * 128 + r_) * DH_ + c8_ * 8); \
        cp16(kb_ + 16384 + so_, Kl + (size_t)((kt) * 128 + r_) * DH_ + c8_ * 8); \
    } \
    CP_COMMIT(); \
} while (0)

    FA_KPF(0);          // group0 = Q + K0
    FA_KPF(1);          // group1 = K1

    // ======= PASS 1: stats only (Q pre-scaled; no S write) =======
    {
        const int wy = wid >> 2, wx = wid & 3;       // 2 x 4 warps, warp 64q x 32k
        const int er = lane >> 2;
#pragma unroll 1
        for (int kt = 0; kt < 16; kt++) {
            if (kt == 15) cp_wait<0>(); else cp_wait<1>();
            __syncthreads();

            float acc[4][4][4];
#pragma unroll
            for (int i = 0; i < 4; i++)
#pragma unroll
                for (int j = 0; j < 4; j++)
#pragma unroll
                    for (int k = 0; k < 4; k++) acc[i][j][k] = 0.0f;

            const uint32_t aQH = sb, aQL = sb + 16384;
            const uint32_t aKH = sb + 32768 + (kt & 1) * 32768, aKL = aKH + 16384;
#pragma unroll
            for (int s = 0; s < 4; s++) {
                const int rA0 = wy * 64 + ((lane >> 3) & 1) * 8 + (lane & 7);
                const int cA = 2 * s + (lane >> 4);
                uint32_t ah[4][4], al[4][4];
#pragma unroll
                for (int mi = 0; mi < 4; mi++) {
                    int r = rA0 + mi * 16;
                    uint32_t off = r * 128 + ((cA ^ (r & 7)) << 4);
                    ldsm4(ah[mi], aQH + off);
                    ldsm4(al[mi], aQL + off);
                }
                uint32_t bhf[2][4], blf[2][4];
                const int cB = 2 * s + ((lane >> 3) & 1);
#pragma unroll
                for (int nh = 0; nh < 2; nh++) {
                    int r = wx * 32 + nh * 16 + ((lane >> 4) & 1) * 8 + (lane & 7);
                    uint32_t off = r * 128 + ((cB ^ (r & 7)) << 4);
                    ldsm4(bhf[nh], aKH + off);
                    ldsm4(blf[nh], aKL + off);
                }
#pragma unroll
                for (int mi = 0; mi < 4; mi++)
#pragma unroll
                    for (int nj = 0; nj < 4; nj++) {
                        uint32_t b0 = bhf[nj >> 1][(nj & 1) * 2], b1 = bhf[nj >> 1][(nj & 1) * 2 + 1];
                        uint32_t c0 = blf[nj >> 1][(nj & 1) * 2], c1 = blf[nj >> 1][(nj & 1) * 2 + 1];
                        mma_bf16(acc[mi][nj], ah[mi], b0, b1);
                        mma_bf16(acc[mi][nj], ah[mi], c0, c1);
                        mma_bf16(acc[mi][nj], al[mi], b0, b1);
                    }
            }

            // warp-local (max, sumexp) partials — one pass, one sync
#pragma unroll
            for (int mi = 0; mi < 4; mi++)
#pragma unroll
                for (int h = 0; h < 2; h++) {
                    float m = -1e30f;
#pragma unroll
                    for (int nj = 0; nj < 4; nj++)
                        m = fmaxf(m, fmaxf(acc[mi][nj][h * 2], acc[mi][nj][h * 2 + 1]));
                    m = fmaxf(m, __shfl_xor_sync(0xffffffffu, m, 1));
                    m = fmaxf(m, __shfl_xor_sync(0xffffffffu, m, 2));
                    float s = 0.0f;
#pragma unroll
                    for (int nj = 0; nj < 4; nj++)
                        s += __expf(acc[mi][nj][h * 2] - m) + __expf(acc[mi][nj][h * 2 + 1] - m);
                    s += __shfl_xor_sync(0xffffffffu, s, 1);
                    s += __shfl_xor_sync(0xffffffffu, s, 2);
                    if ((lane & 3) == 0)
                        s_red[wy * 64 + mi * 16 + h * 8 + er][wx] = make_float2(m, s);
                }
            __syncthreads();
            if (t < 128) {
                float2 p0 = s_red[t][0], p1 = s_red[t][1], p2 = s_red[t][2], p3 = s_red[t][3];
                float mt = fmaxf(fmaxf(p0.x, p1.x), fmaxf(p2.x, p3.x));
                float st = p0.y * __expf(p0.x - mt) + p1.y * __expf(p1.x - mt)
                         + p2.y * __expf(p2.x - mt) + p3.y * __expf(p3.x - mt);
                float mo = sm_m[t];
                float mn = fmaxf(mo, mt);
                sm_s[t] = sm_s[t] * __expf(mo - mn) + st * __expf(mt - mn);
                sm_m[t] = mn;
            }
            if (kt + 2 < 16) FA_KPF(kt + 2);
        }
    }
    __syncthreads();
    if (t < 128) sm_i[t] = 1.0f / sm_s[t];
    __syncthreads();

    // ======= PASS 2 (flash): recompute S per warp-row-tile, p in regs, O=p@V ===
    {
        const uint32_t aQH = sb, aQL = sb + 16384;
        const uint32_t KB[2] = { sb + 32768, sb + 49152 };   // hi @0, lo @+8192
        const uint32_t VB[2] = { sb + 65536, sb + 81920 };
        const int r0 = wid * 16 + (lane >> 2), r1 = r0 + 8;  // this thread's q rows (local)
        const float m0 = sm_m[r0], i0 = sm_i[r0];
        const float m1 = sm_m[r1], i1 = sm_i[r1];

#define KVPF(c) do { \
    const int kc_ = (c) * 64; \
    uint32_t kb_ = KB[(c) & 1], vb_ = VB[(c) & 1]; \
    _Pragma("unroll") \
    for (int i_ = 0; i_ < 2; i_++) { \
        int e_ = i_ * 256 + t, r_ = e_ >> 3, c8_ = e_ & 7; \
        uint32_t so_ = r_ * 128 + ((c8_ ^ (r_ & 7)) << 4); \
        const size_t gk_ = (size_t)(kc_ + r_) * DH_ + c8_ * 8; \
        cp16(kb_ + so_,        Kh + gk_); \
        cp16(kb_ + 8192 + so_, Kl + gk_); \
        cp16(vb_ + so_,        Vh + gk_); \
        cp16(vb_ + 8192 + so_, Vl + gk_); \
    } \
    CP_COMMIT(); \
} while (0)

        float accO[8][4];
#pragma unroll
        for (int j = 0; j < 8; j++)
#pragma unroll
            for (int k = 0; k < 4; k++) accO[j][k] = 0.0f;

        KVPF(0);
#pragma unroll 1
        for (int c = 0; c < 32; c++) {
            if (c + 1 < 32) KVPF(c + 1);
            if (c + 1 < 32) cp_wait<1>(); else cp_wait<0>();
            __syncthreads();

            const uint32_t kH = KB[c & 1], kL = kH + 8192;
            const uint32_t vH = VB[c & 1], vL = vH + 8192;

            // ---- MMA1: S[16q x 64k] per warp (Q from smem, K from smem) ----
            float accS[8][4];
#pragma unroll
            for (int j = 0; j < 8; j++)
#pragma unroll
                for (int k = 0; k < 4; k++) accS[j][k] = 0.0f;

            const int rQ = wid * 16 + ((lane >> 3) & 1) * 8 + (lane & 7);
            const int rKb = ((lane >> 4) & 1) * 8 + (lane & 7);
#pragma unroll
            for (int s = 0; s < 4; s++) {
                const int cA = 2 * s + (lane >> 4);
                uint32_t qh[4], ql[4];
                {
                    uint32_t off = rQ * 128 + ((cA ^ (rQ & 7)) << 4);
                    ldsm4(qh, aQH + off);
                    ldsm4(ql, aQL + off);
                }
                const int cB = 2 * s + ((lane >> 3) & 1);
#pragma unroll
                for (int kb = 0; kb < 4; kb++) {
                    uint32_t bhf[4], blf[4];
                    int r = kb * 16 + rKb;
                    uint32_t off = r * 128 + ((cB ^ (r & 7)) << 4);
                    ldsm4(bhf, kH + off);
                    ldsm4(blf, kL + off);
#pragma unroll
                    for (int h2 = 0; h2 < 2; h2++) {
                        const int nj = kb * 2 + h2;
                        uint32_t b0 = bhf[h2 * 2], b1 = bhf[h2 * 2 + 1];
                        uint32_t c0 = blf[h2 * 2], c1 = blf[h2 * 2 + 1];
                        mma_bf16(accS[nj], qh, b0, b1);
                        mma_bf16(accS[nj], qh, c0, c1);
                        mma_bf16(accS[nj], ql, b0, b1);
                    }
                }
            }

            // ---- transform: p = exp(S - m) * inv; write p; repack as A-frags ----
            const int kc = c * 64;
            uint32_t pa_h[4][4], pa_l[4][4];
#pragma unroll
            for (int nj = 0; nj < 8; nj++) {
                float p0 = __expf(accS[nj][0] - m0) * i0;
                float p1 = __expf(accS[nj][1] - m0) * i0;
                float p2 = __expf(accS[nj][2] - m1) * i1;
                float p3 = __expf(accS[nj][3] - m1) * i1;
                const int col = kc + nj * 8 + (lane & 3) * 2;
                *(float2*)(A + (size_t)(q0 + r0) * S_ + col) = make_float2(p0, p1);
                *(float2*)(A + (size_t)(q0 + r1) * S_ + col) = make_float2(p2, p3);
                const int s2 = nj >> 1, qh2 = nj & 1;
                split2(p0, p1, pa_h[s2][qh2 * 2 + 0], pa_l[s2][qh2 * 2 + 0]);
                split2(p2, p3, pa_h[s2][qh2 * 2 + 1], pa_l[s2][qh2 * 2 + 1]);
            }

            // ---- MMA2: O[16q x 64d] += p @ V (V from smem, p from regs) ----
            const int rVb = ((lane >> 3) & 1) * 8 + (lane & 7);
#pragma unroll
            for (int s = 0; s < 4; s++) {
                const int rB = 16 * s + rVb;
#pragma unroll
                for (int db = 0; db < 4; db++) {
                    uint32_t vhf[4], vlf[4];
                    int cB = db * 2 + ((lane >> 4) & 1);
                    uint32_t off = rB * 128 + ((cB ^ (rB & 7)) << 4);
                    ldsm4t(vhf, vH + off);
                    ldsm4t(vlf, vL + off);
#pragma unroll
                    for (int h2 = 0; h2 < 2; h2++) {
                        const int dj = db * 2 + h2;
                        uint32_t b0 = vhf[h2 * 2], b1 = vhf[h2 * 2 + 1];
                        uint32_t c0 = vlf[h2 * 2], c1 = vlf[h2 * 2 + 1];
                        mma_bf16(accO[dj], pa_h[s], b0, b1);
                        mma_bf16(accO[dj], pa_h[s], c0, c1);
                        mma_bf16(accO[dj], pa_l[s], b0, b1);
                    }
                }
            }
            __syncthreads();   // buffer c&1 free for prefetch of c+2
        }

        // epilogue: O -> g_cat (split)
        const int bb = bh >> 4, hh = bh & (H_ - 1);
#pragma unroll
        for (int dj = 0; dj < 8; dj++) {
            const int dd = dj * 8 + (lane & 3) * 2;
            uint32_t hv, lv;
            split2(accO[dj][0], accO[dj][1], hv, lv);
            size_t idx = ((size_t)(bb * S_ + q0 + r0)) * D_ + hh * DH_ + dd;
            *(uint32_t*)(g_cat_h + idx) = hv;
            *(uint32_t*)(g_cat_l + idx) = lv;
            split2(accO[dj][2], accO[dj][3], hv, lv);
            idx = ((size_t)(bb * S_ + q0 + r1)) * D_ + hh * DH_ + dd;
            *(uint32_t*)(g_cat_h + idx) = hv;
            *(uint32_t*)(g_cat_l + idx) = lv;
        }
    }
}

// ---------------- launch ------------------------------------------------------
extern "C" void kernel_launch(void* const* d_in, const int* in_sizes, int n_in,
                              void* d_out, int out_size)
{
    const float* q  = (const float*)d_in[0];
    const float* k  = (const float*)d_in[1];
    const float* v  = (const float*)d_in[2];
    const float* Wq = (const float*)d_in[3];
    const float* bq = (const float*)d_in[4];
    const float* Wk = (const float*)d_in[5];
    const float* bk = (const float*)d_in[6];
    const float* Wv = (const float*)d_in[7];
    const float* bv = (const float*)d_in[8];
    const float* Wc = (const float*)d_in[9];
    const float* bc = (const float*)d_in[10];

    float* out  = (float*)d_out;
    float* attn = out + OUT_ELEMS;

    const int SM_PROJ = 196608;
    const int SM_FA   = 98304;
    cudaFuncSetAttribute(proj_tc,    cudaFuncAttributeMaxDynamicSharedMemorySize, SM_PROJ);
    cudaFuncSetAttribute(fused_attn, cudaFuncAttributeMaxDynamicSharedMemorySize, SM_FA);

    split_all<<<16384, 256>>>(q, k, v, Wq, Wk, Wv, Wc);

    proj_tc<<<dim3(8, 32, 3), 256, SM_PROJ>>>(bq, bk, bv, bc, nullptr, 0);

    fused_attn<<<dim3(16, 32), 256, SM_FA>>>(attn);

    proj_tc<<<dim3(8, 32, 1), 256, SM_PROJ>>>(bq, bk, bv, bc, out, 3);
}

// round 17
// speedup vs baseline: 1.5359x; 1.0059x over previous
#include <cuda_runtime.h>
#include <cuda_bf16.h>
#include <math.h>
#include <stdint.h>

#define B_ 2
#define S_ 2048
#define D_ 1024
#define H_ 16
#define DH_ 64
#define NTOK 4096
#define OUT_ELEMS ((size_t)NTOK * D_)

// ---------------- pre-split bf16 hi/lo scratch -------------------------------
__device__ __nv_bfloat16 g_xs_h[3][(size_t)NTOK * D_];
__device__ __nv_bfloat16 g_xs_l[3][(size_t)NTOK * D_];
__device__ __nv_bfloat16 g_ws_h[4][(size_t)D_ * D_];
__device__ __nv_bfloat16 g_ws_l[4][(size_t)D_ * D_];
__device__ __nv_bfloat16 g_hd_h[3][(size_t)NTOK * D_];   // head-split q/k/v (q pre-scaled 0.125)
__device__ __nv_bfloat16 g_hd_l[3][(size_t)NTOK * D_];
__device__ __nv_bfloat16 g_cat_h[(size_t)NTOK * D_];
__device__ __nv_bfloat16 g_cat_l[(size_t)NTOK * D_];

// ---------------- helpers -----------------------------------------------------
__device__ __forceinline__ uint32_t smem_u32(const void* p) {
    uint32_t a;
    asm("{ .reg .u64 t; cvta.to.shared.u64 t, %1; cvt.u32.u64 %0, t; }" : "=r"(a) : "l"(p));
    return a;
}
__device__ __forceinline__ void mma_bf16(float c[4], const uint32_t a[4],
                                         uint32_t b0, uint32_t b1) {
    asm volatile("mma.sync.aligned.m16n8k16.row.col.f32.bf16.bf16.f32 "
        "{%0,%1,%2,%3}, {%4,%5,%6,%7}, {%8,%9}, {%0,%1,%2,%3};"
        : "+f"(c[0]), "+f"(c[1]), "+f"(c[2]), "+f"(c[3])
        : "r"(a[0]), "r"(a[1]), "r"(a[2]), "r"(a[3]), "r"(b0), "r"(b1));
}
__device__ __forceinline__ void ldsm4(uint32_t r[4], uint32_t a) {
    asm volatile("ldmatrix.sync.aligned.m8n8.x4.shared.b16 {%0,%1,%2,%3}, [%4];"
        : "=r"(r[0]), "=r"(r[1]), "=r"(r[2]), "=r"(r[3]) : "r"(a));
}
__device__ __forceinline__ void ldsm4t(uint32_t r[4], uint32_t a) {
    asm volatile("ldmatrix.sync.aligned.m8n8.x4.trans.shared.b16 {%0,%1,%2,%3}, [%4];"
        : "=r"(r[0]), "=r"(r[1]), "=r"(r[2]), "=r"(r[3]) : "r"(a));
}
__device__ __forceinline__ void split2(float x, float y, uint32_t& hi, uint32_t& lo) {
    __nv_bfloat16 hx = __float2bfloat16(x), hy = __float2bfloat16(y);
    __nv_bfloat16 lx = __float2bfloat16(x - __bfloat162float(hx));
    __nv_bfloat16 ly = __float2bfloat16(y - __bfloat162float(hy));
    __nv_bfloat162 h(hx, hy), l(lx, ly);
    hi = *(uint32_t*)&h;
    lo = *(uint32_t*)&l;
}
__device__ __forceinline__ void cp16(uint32_t smem, const void* g) {
    asm volatile("cp.async.cg.shared.global [%0], [%1], 16;" :: "r"(smem), "l"(g));
}
#define CP_COMMIT() asm volatile("cp.async.commit_group;" ::: "memory")
template<int N> __device__ __forceinline__ void cp_wait() {
    asm volatile("cp.async.wait_group %0;" :: "n"(N) : "memory");
}

// ---------------- prep: split inputs + weights --------------------------------
__global__ void __launch_bounds__(256) split_all(
    const float* __restrict__ q, const float* __restrict__ k, const float* __restrict__ v,
    const float* __restrict__ wq, const float* __restrict__ wk,
    const float* __restrict__ wv, const float* __restrict__ wc)
{
    int i = blockIdx.x * 256 + threadIdx.x;          // float4 index
    const float* src;
    __nv_bfloat16 *dh, *dl;
    int off;
    if (i < 3 * 1048576) {
        int ti = i >> 20; off = i & 1048575;
        src = (ti == 0) ? q : (ti == 1) ? k : v;
        dh = g_xs_h[ti]; dl = g_xs_l[ti];
    } else {
        int j = i - 3145728;
        int ti = j >> 18; off = j & 262143;
        src = (ti == 0) ? wq : (ti == 1) ? wk : (ti == 2) ? wv : wc;
        dh = g_ws_h[ti]; dl = g_ws_l[ti];
    }
    float4 x = ((const float4*)src)[off];
    uint32_t h01, l01, h23, l23;
    split2(x.x, x.y, h01, l01);
    split2(x.z, x.w, h23, l23);
    ((uint2*)dh)[off] = make_uint2(h01, h23);
    ((uint2*)dl)[off] = make_uint2(l01, l23);
}

// ---------------- projection GEMM (chunk 64, 3-stage, single sync/chunk) ------
// mode 0 pre-scales the output by 0.125 (softmax scale folded into Q; exact).
__global__ void __launch_bounds__(256, 1)
proj_tc(const float* __restrict__ bq, const float* __restrict__ bk,
        const float* __restrict__ bv, const float* __restrict__ bc,
        float* __restrict__ Yout, int mode_base)
{
    extern __shared__ __align__(1024) char smp[];
    uint32_t sb = smem_u32(smp);
    const int t = threadIdx.x, lane = t & 31, wid = t >> 5;
    const int wy = wid >> 2, wx = wid & 3;
    const int mode = mode_base + blockIdx.z;
    const __nv_bfloat16 *Xh, *Xl;
    if (mode < 3) { Xh = g_xs_h[mode]; Xl = g_xs_l[mode]; }
    else          { Xh = g_cat_h;      Xl = g_cat_l; }
    const __nv_bfloat16 *Wh = g_ws_h[mode], *Wl = g_ws_l[mode];
    const float* bias = (mode == 0) ? bq : (mode == 1) ? bk : (mode == 2) ? bv : bc;
    const int bm = blockIdx.y * 128, bn = blockIdx.x * 128;

    float acc[4][4][4];
#pragma unroll
    for (int i = 0; i < 4; i++)
#pragma unroll
        for (int j = 0; j < 4; j++)
#pragma unroll
            for (int k = 0; k < 4; k++) acc[i][j][k] = 0.0f;

#define PJ_PF(c) do { \
    const int kc_ = (c) * 64; \
    uint32_t bo_ = sb + ((c) % 3) * 65536; \
    _Pragma("unroll") \
    for (int i_ = 0; i_ < 4; i_++) { \
        int e_ = i_ * 256 + t, r_ = e_ >> 3, c8_ = e_ & 7; \
        uint32_t so_ = r_ * 128 + ((c8_ ^ (r_ & 7)) << 4); \
        const size_t g_ = (size_t)(bm + r_) * D_ + kc_ + c8_ * 8; \
        cp16(bo_ + so_,         Xh + g_); \
        cp16(bo_ + 16384 + so_, Xl + g_); \
    } \
    _Pragma("unroll") \
    for (int i_ = 0; i_ < 4; i_++) { \
        int e_ = i_ * 256 + t, k_ = e_ >> 4, b_ = e_ & 15; \
        uint32_t so_ = k_ * 256 + ((b_ ^ (k_ & 7)) << 4); \
        const size_t g_ = (size_t)(kc_ + k_) * D_ + bn + b_ * 8; \
        cp16(bo_ + 32768 + so_, Wh + g_); \
        cp16(bo_ + 49152 + so_, Wl + g_); \
    } \
    CP_COMMIT(); \
} while (0)

#define PJ_MMA(base) do { \
    uint32_t aAH = (base), aAL = (base) + 16384, aBH = (base) + 32768, aBL = (base) + 49152; \
    _Pragma("unroll") \
    for (int s = 0; s < 4; s++) { \
        const int rA0 = wy * 64 + ((lane >> 3) & 1) * 8 + (lane & 7); \
        const int cA = 2 * s + (lane >> 4); \
        uint32_t ah[4][4], al[4][4]; \
        _Pragma("unroll") \
        for (int mi = 0; mi < 4; mi++) { \
            int r = rA0 + mi * 16; \
            uint32_t off = r * 128 + ((cA ^ (r & 7)) << 4); \
            ldsm4(ah[mi], aAH + off); \
            ldsm4(al[mi], aAL + off); \
        } \
        const int rB = 16 * s + ((lane >> 3) & 1) * 8 + (lane & 7); \
        uint32_t bh[2][4], bl[2][4]; \
        _Pragma("unroll") \
        for (int nh = 0; nh < 2; nh++) { \
            int cB = ((wx * 32 + nh * 16) >> 3) + ((lane >> 4) & 1); \
            uint32_t off = rB * 256 + ((cB ^ (rB & 7)) << 4); \
            ldsm4t(bh[nh], aBH + off); \
            ldsm4t(bl[nh], aBL + off); \
        } \
        _Pragma("unroll") \
        for (int mi = 0; mi < 4; mi++) \
            _Pragma("unroll") \
            for (int nj = 0; nj < 4; nj++) { \
                uint32_t bh0 = bh[nj >> 1][(nj & 1) * 2], bh1 = bh[nj >> 1][(nj & 1) * 2 + 1]; \
                uint32_t bl0 = bl[nj >> 1][(nj & 1) * 2], bl1 = bl[nj >> 1][(nj & 1) * 2 + 1]; \
                mma_bf16(acc[mi][nj], ah[mi], bh0, bh1); \
                mma_bf16(acc[mi][nj], ah[mi], bl0, bl1); \
                mma_bf16(acc[mi][nj], al[mi], bh0, bh1); \
            } \
    } \
} while (0)

    PJ_PF(0); PJ_PF(1);
#pragma unroll 1
    for (int c = 0; c < 16; c++) {
        if (c < 15) cp_wait<1>(); else cp_wait<0>();
        __syncthreads();                     // all warps finished MMA(c-1) + chunk c visible
        if (c + 2 < 16) PJ_PF(c + 2);        // safe: (c+2)%3 buffer was last read in MMA(c-1)
        PJ_MMA(sb + (c % 3) * 65536);
    }

    const int er = lane >> 2, ec = (lane & 3) * 2;
    if (mode < 3) {
        const float sc = (mode == 0) ? 0.125f : 1.0f;   // fold softmax scale into Q (exact)
        __nv_bfloat16* dh = g_hd_h[mode];
        __nv_bfloat16* dl = g_hd_l[mode];
#pragma unroll
        for (int mi = 0; mi < 4; mi++)
#pragma unroll
            for (int nj = 0; nj < 4; nj++) {
                const int col = bn + wx * 32 + nj * 8 + ec;
                const float b0 = __ldg(bias + col), b1 = __ldg(bias + col + 1);
                const int row0 = bm + wy * 64 + mi * 16 + er;
#pragma unroll
                for (int h = 0; h < 2; h++) {
                    const int row = row0 + h * 8;
                    uint32_t hv, lv;
                    split2((acc[mi][nj][h * 2] + b0) * sc, (acc[mi][nj][h * 2 + 1] + b1) * sc, hv, lv);
                    int bb = row >> 11, ss = row & (S_ - 1), hh = col >> 6, dd = col & (DH_ - 1);
                    size_t idx = (((size_t)(bb * H_ + hh)) * S_ + ss) * DH_ + dd;
                    *(uint32_t*)(dh + idx) = hv;
                    *(uint32_t*)(dl + idx) = lv;
                }
            }
    } else {
#pragma unroll
        for (int mi = 0; mi < 4; mi++)
#pragma unroll
            for (int nj = 0; nj < 4; nj++) {
                const int col = bn + wx * 32 + nj * 8 + ec;
                const float b0 = __ldg(bias + col), b1 = __ldg(bias + col + 1);
                const int row0 = bm + wy * 64 + mi * 16 + er;
#pragma unroll
                for (int h = 0; h < 2; h++) {
                    float2 v = make_float2(acc[mi][nj][h * 2] + b0, acc[mi][nj][h * 2 + 1] + b1);
                    *(float2*)(Yout + (size_t)(row0 + h * 8) * D_ + col) = v;
                }
            }
    }
}

// ---------------- fused attention: pass1 stats-only, pass2 flash --------------
// SMEM (96KB):
//  Q @0 (hi 16K, lo 16K)                                   [persistent, both passes]
//  pass1: K tiles 128 rows: buf0 @32K, buf1 @64K (hi 16K, lo 16K each)
//  pass2: K bufs @32K,@48K (hi 8K, lo 8K); V bufs @64K,@80K (hi 8K, lo 8K)
__global__ void __launch_bounds__(256, 2) fused_attn(float* __restrict__ attn)
{
    extern __shared__ __align__(1024) char smp[];
    __shared__ float2 s_red[128][4];
    __shared__ float sm_m[128], sm_s[128], sm_i[128];
    uint32_t sb = smem_u32(smp);
    const int t = threadIdx.x, lane = t & 31, wid = t >> 5;
    const int bh = blockIdx.y, q0 = blockIdx.x * 128;
    const __nv_bfloat16* Qh = g_hd_h[0] + (size_t)bh * S_ * DH_;
    const __nv_bfloat16* Ql = g_hd_l[0] + (size_t)bh * S_ * DH_;
    const __nv_bfloat16* Kh = g_hd_h[1] + (size_t)bh * S_ * DH_;
    const __nv_bfloat16* Kl = g_hd_l[1] + (size_t)bh * S_ * DH_;
    const __nv_bfloat16* Vh = g_hd_h[2] + (size_t)bh * S_ * DH_;
    const __nv_bfloat16* Vl = g_hd_l[2] + (size_t)bh * S_ * DH_;
    float* A = attn + (size_t)bh * S_ * S_;

    if (t < 128) { sm_m[t] = -1e30f; sm_s[t] = 0.0f; }

    // ---- load Q (group with K0) ----
#pragma unroll
    for (int i = 0; i < 4; i++) {
        int e = i * 256 + t, r = e >> 3, c8 = e & 7;
        uint32_t so = r * 128 + ((c8 ^ (r & 7)) << 4);
        cp16(sb + so,         Qh + (size_t)(q0 + r) * DH_ + c8 * 8);
        cp16(sb + 16384 + so, Ql + (size_t)(q0 + r) * DH_ + c8 * 8);
    }
#define FA_KPF(kt) do { \
    uint32_t kb_ = sb + 32768 + ((kt) & 1) * 32768; \
    _Pragma("unroll") \
    for (int i_ = 0; i_ < 4; i_++) { \
        int e_ = i_ * 256 + t, r_ = e_ >> 3, c8_ = e_ & 7; \
        uint32_t so_ = r_ * 128 + ((c8_ ^ (r_ & 7)) << 4); \
        cp16(kb_ + so_,         Kh + (size_t)((kt) * 128 + r_) * DH_ + c8_ * 8); \
        cp16(kb_ + 16384 + so_, Kl + (size_t)((kt) * 128 + r_) * DH_ + c8_ * 8); \
    } \
    CP_COMMIT(); \
} while (0)

    FA_KPF(0);          // group0 = Q + K0
    FA_KPF(1);          // group1 = K1

    // ======= PASS 1: stats only (Q pre-scaled; no S write) =======
    {
        const int wy = wid >> 2, wx = wid & 3;       // 2 x 4 warps, warp 64q x 32k
        const int er = lane >> 2;
#pragma unroll 1
        for (int kt = 0; kt < 16; kt++) {
            if (kt == 15) cp_wait<0>(); else cp_wait<1>();
            __syncthreads();

            float acc[4][4][4];
#pragma unroll
            for (int i = 0; i < 4; i++)
#pragma unroll
                for (int j = 0; j < 4; j++)
#pragma unroll
                    for (int k = 0; k < 4; k++) acc[i][j][k] = 0.0f;

            const uint32_t aQH = sb, aQL = sb + 16384;
            const uint32_t aKH = sb + 32768 + (kt & 1) * 32768, aKL = aKH + 16384;
#pragma unroll
            for (int s = 0; s < 4; s++) {
                const int rA0 = wy * 64 + ((lane >> 3) & 1) * 8 + (lane & 7);
                const int cA = 2 * s + (lane >> 4);
                uint32_t ah[4][4], al[4][4];
#pragma unroll
                for (int mi = 0; mi < 4; mi++) {
                    int r = rA0 + mi * 16;
                    uint32_t off = r * 128 + ((cA ^ (r & 7)) << 4);
                    ldsm4(ah[mi], aQH + off);
                    ldsm4(al[mi], aQL + off);
                }
                uint32_t bhf[2][4], blf[2][4];
                const int cB = 2 * s + ((lane >> 3) & 1);
#pragma unroll
                for (int nh = 0; nh < 2; nh++) {
                    int r = wx * 32 + nh * 16 + ((lane >> 4) & 1) * 8 + (lane & 7);
                    uint32_t off = r * 128 + ((cB ^ (r & 7)) << 4);
                    ldsm4(bhf[nh], aKH + off);
                    ldsm4(blf[nh], aKL + off);
                }
#pragma unroll
                for (int mi = 0; mi < 4; mi++)
#pragma unroll
                    for (int nj = 0; nj < 4; nj++) {
                        uint32_t b0 = bhf[nj >> 1][(nj & 1) * 2], b1 = bhf[nj >> 1][(nj & 1) * 2 + 1];
                        uint32_t c0 = blf[nj >> 1][(nj & 1) * 2], c1 = blf[nj >> 1][(nj & 1) * 2 + 1];
                        mma_bf16(acc[mi][nj], ah[mi], b0, b1);
                        mma_bf16(acc[mi][nj], ah[mi], c0, c1);
                        mma_bf16(acc[mi][nj], al[mi], b0, b1);
                    }
            }

            // warp-local (max, sumexp) partials — one pass, one sync
#pragma unroll
            for (int mi = 0; mi < 4; mi++)
#pragma unroll
                for (int h = 0; h < 2; h++) {
                    float m = -1e30f;
#pragma unroll
                    for (int nj = 0; nj < 4; nj++)
                        m = fmaxf(m, fmaxf(acc[mi][nj][h * 2], acc[mi][nj][h * 2 + 1]));
                    m = fmaxf(m, __shfl_xor_sync(0xffffffffu, m, 1));
                    m = fmaxf(m, __shfl_xor_sync(0xffffffffu, m, 2));
                    float s = 0.0f;
#pragma unroll
                    for (int nj = 0; nj < 4; nj++)
                        s += __expf(acc[mi][nj][h * 2] - m) + __expf(acc[mi][nj][h * 2 + 1] - m);
                    s += __shfl_xor_sync(0xffffffffu, s, 1);
                    s += __shfl_xor_sync(0xffffffffu, s, 2);
                    if ((lane & 3) == 0)
                        s_red[wy * 64 + mi * 16 + h * 8 + er][wx] = make_float2(m, s);
                }
            __syncthreads();
            if (t < 128) {
                float2 p0 = s_red[t][0], p1 = s_red[t][1], p2 = s_red[t][2], p3 = s_red[t][3];
                float mt = fmaxf(fmaxf(p0.x, p1.x), fmaxf(p2.x, p3.x));
                float st = p0.y * __expf(p0.x - mt) + p1.y * __expf(p1.x - mt)
                         + p2.y * __expf(p2.x - mt) + p3.y * __expf(p3.x - mt);
                float mo = sm_m[t];
                float mn = fmaxf(mo, mt);
                sm_s[t] = sm_s[t] * __expf(mo - mn) + st * __expf(mt - mn);
                sm_m[t] = mn;
            }
            if (kt + 2 < 16) FA_KPF(kt + 2);   // after stats sync: all warps done with buf (kt&1)
        }
    }
    __syncthreads();
    if (t < 128) sm_i[t] = 1.0f / sm_s[t];
    __syncthreads();

    // ======= PASS 2 (flash): recompute S per warp tile, p in regs, O=p@V ======
    {
        const uint32_t aQH = sb, aQL = sb + 16384;
        const uint32_t KB[2] = { sb + 32768, sb + 49152 };   // hi @0, lo @+8192
        const uint32_t VB[2] = { sb + 65536, sb + 81920 };
        const int r0 = wid * 16 + (lane >> 2), r1 = r0 + 8;  // this thread's q rows (local)
        const float m0 = sm_m[r0], i0 = sm_i[r0];
        const float m1 = sm_m[r1], i1 = sm_i[r1];

#define KVPF(c) do { \
    const int kc_ = (c) * 64; \
    uint32_t kb_ = KB[(c) & 1], vb_ = VB[(c) & 1]; \
    _Pragma("unroll") \
    for (int i_ = 0; i_ < 2; i_++) { \
        int e_ = i_ * 256 + t, r_ = e_ >> 3, c8_ = e_ & 7; \
        uint32_t so_ = r_ * 128 + ((c8_ ^ (r_ & 7)) << 4); \
        const size_t gk_ = (size_t)(kc_ + r_) * DH_ + c8_ * 8; \
        cp16(kb_ + so_,        Kh + gk_); \
        cp16(kb_ + 8192 + so_, Kl + gk_); \
        cp16(vb_ + so_,        Vh + gk_); \
        cp16(vb_ + 8192 + so_, Vl + gk_); \
    } \
    CP_COMMIT(); \
} while (0)

        float accO[8][4];
#pragma unroll
        for (int j = 0; j < 8; j++)
#pragma unroll
            for (int k = 0; k < 4; k++) accO[j][k] = 0.0f;

        KVPF(0);
#pragma unroll 1
        for (int c = 0; c < 32; c++) {
            cp_wait<0>();
            __syncthreads();                 // all warps done with MMA(c-1); chunk c visible
            if (c + 1 < 32) KVPF(c + 1);     // other buffer; overlapped with MMA(c)

            const uint32_t kH = KB[c & 1], kL = kH + 8192;
            const uint32_t vH = VB[c & 1], vL = vH + 8192;

            // ---- MMA1: S[16q x 64k] per warp ----
            float accS[8][4];
#pragma unroll
            for (int j = 0; j < 8; j++)
#pragma unroll
                for (int k = 0; k < 4; k++) accS[j][k] = 0.0f;

            const int rQ = wid * 16 + ((lane >> 3) & 1) * 8 + (lane & 7);
            const int rKb = ((lane >> 4) & 1) * 8 + (lane & 7);
#pragma unroll
            for (int s = 0; s < 4; s++) {
                const int cA = 2 * s + (lane >> 4);
                uint32_t qh[4], ql[4];
                {
                    uint32_t off = rQ * 128 + ((cA ^ (rQ & 7)) << 4);
                    ldsm4(qh, aQH + off);
                    ldsm4(ql, aQL + off);
                }
                const int cB = 2 * s + ((lane >> 3) & 1);
#pragma unroll
                for (int kb = 0; kb < 4; kb++) {
                    uint32_t bhf[4], blf[4];
                    int r = kb * 16 + rKb;
                    uint32_t off = r * 128 + ((cB ^ (r & 7)) << 4);
                    ldsm4(bhf, kH + off);
                    ldsm4(blf, kL + off);
#pragma unroll
                    for (int h2 = 0; h2 < 2; h2++) {
                        const int nj = kb * 2 + h2;
                        uint32_t b0 = bhf[h2 * 2], b1 = bhf[h2 * 2 + 1];
                        uint32_t c0 = blf[h2 * 2], c1 = blf[h2 * 2 + 1];
                        mma_bf16(accS[nj], qh, b0, b1);
                        mma_bf16(accS[nj], qh, c0, c1);
                        mma_bf16(accS[nj], ql, b0, b1);
                    }
                }
            }

            // ---- per-s: transform p (8 regs live), write p, MMA2 for that s ----
            const int kc = c * 64;
            const int rVb = ((lane >> 3) & 1) * 8 + (lane & 7);
#pragma unroll
            for (int s = 0; s < 4; s++) {
                uint32_t pah[4], pal[4];
#pragma unroll
                for (int h2 = 0; h2 < 2; h2++) {
                    const int nj = s * 2 + h2;
                    float p0 = __expf(accS[nj][0] - m0) * i0;
                    float p1 = __expf(accS[nj][1] - m0) * i0;
                    float p2 = __expf(accS[nj][2] - m1) * i1;
                    float p3 = __expf(accS[nj][3] - m1) * i1;
                    const int col = kc + nj * 8 + (lane & 3) * 2;
                    *(float2*)(A + (size_t)(q0 + r0) * S_ + col) = make_float2(p0, p1);
                    *(float2*)(A + (size_t)(q0 + r1) * S_ + col) = make_float2(p2, p3);
                    split2(p0, p1, pah[h2 * 2 + 0], pal[h2 * 2 + 0]);
                    split2(p2, p3, pah[h2 * 2 + 1], pal[h2 * 2 + 1]);
                }
                const int rB = 16 * s + rVb;
#pragma unroll
                for (int db = 0; db < 4; db++) {
                    uint32_t vhf[4], vlf[4];
                    int cB = db * 2 + ((lane >> 4) & 1);
                    uint32_t off = rB * 128 + ((cB ^ (rB & 7)) << 4);
                    ldsm4t(vhf, vH + off);
                    ldsm4t(vlf, vL + off);
#pragma unroll
                    for (int h2 = 0; h2 < 2; h2++) {
                        const int dj = db * 2 + h2;
                        uint32_t b0 = vhf[h2 * 2], b1 = vhf[h2 * 2 + 1];
                        uint32_t c0 = vlf[h2 * 2], c1 = vlf[h2 * 2 + 1];
                        mma_bf16(accO[dj], pah, b0, b1);
                        mma_bf16(accO[dj], pah, c0, c1);
                        mma_bf16(accO[dj], pal, b0, b1);
                    }
                }
            }
        }

        // epilogue: O -> g_cat (split)
        const int bb = bh >> 4, hh = bh & (H_ - 1);
#pragma unroll
        for (int dj = 0; dj < 8; dj++) {
            const int dd = dj * 8 + (lane & 3) * 2;
            uint32_t hv, lv;
            split2(accO[dj][0], accO[dj][1], hv, lv);
            size_t idx = ((size_t)(bb * S_ + q0 + r0)) * D_ + hh * DH_ + dd;
            *(uint32_t*)(g_cat_h + idx) = hv;
            *(uint32_t*)(g_cat_l + idx) = lv;
            split2(accO[dj][2], accO[dj][3], hv, lv);
            idx = ((size_t)(bb * S_ + q0 + r1)) * D_ + hh * DH_ + dd;
            *(uint32_t*)(g_cat_h + idx) = hv;
            *(uint32_t*)(g_cat_l + idx) = lv;
        }
    }
}

// ---------------- launch ------------------------------------------------------
extern "C" void kernel_launch(void* const* d_in, const int* in_sizes, int n_in,
                              void* d_out, int out_size)
{
    const float* q  = (const float*)d_in[0];
    const float* k  = (const float*)d_in[1];
    const float* v  = (const float*)d_in[2];
    const float* Wq = (const float*)d_in[3];
    const float* bq = (const float*)d_in[4];
    const float* Wk = (const float*)d_in[5];
    const float* bk = (const float*)d_in[6];
    const float* Wv = (const float*)d_in[7];
    const float* bv = (const float*)d_in[8];
    const float* Wc = (const float*)d_in[9];
    const float* bc = (const float*)d_in[10];

    float* out  = (float*)d_out;
    float* attn = out + OUT_ELEMS;

    const int SM_PROJ = 196608;
    const int SM_FA   = 98304;
    cudaFuncSetAttribute(proj_tc,    cudaFuncAttributeMaxDynamicSharedMemorySize, SM_PROJ);
    cudaFuncSetAttribute(fused_attn, cudaFuncAttributeMaxDynamicSharedMemorySize, SM_FA);

    split_all<<<16384, 256>>>(q, k, v, Wq, Wk, Wv, Wc);

    proj_tc<<<dim3(8, 32, 3), 256, SM_PROJ>>>(bq, bk, bv, bc, nullptr, 0);

    fused_attn<<<dim3(16, 32), 256, SM_FA>>>(attn);

    proj_tc<<<dim3(8, 32, 1), 256, SM_PROJ>>>(bq, bk, bv, bc, out, 3);
}